// round 11
// baseline (speedup 1.0000x reference)
#include <cuda_runtime.h>
#include <cuda_bf16.h>
#include <cstdint>

// Problem dims
#define B_  2
#define S_  2048
#define D_  1024
#define H_  16
#define HD_ 64
#define GM  (B_ * S_)   // 4096
#define GN  D_          // 1024
#define GK  D_          // 1024

// softmax scale folded into Q: 1/sqrt(64) * log2(e)
#define QSCALE 0.18033688011112043f

// ---------------------------------------------------------------------------
// Scratch (__device__ globals; allocation-free rule)
// ---------------------------------------------------------------------------
__device__ __nv_bfloat16 g_x_hi[GM * GK];
__device__ __nv_bfloat16 g_x_lo[GM * GK];
__device__ __nv_bfloat16 g_qh[B_ * H_ * S_ * HD_];   // [B,H,S,HD] (pre-scaled)
__device__ __nv_bfloat16 g_ql[B_ * H_ * S_ * HD_];
__device__ __nv_bfloat16 g_kh[B_ * H_ * S_ * HD_];
__device__ __nv_bfloat16 g_kl[B_ * H_ * S_ * HD_];
__device__ __nv_bfloat16 g_vh[B_ * H_ * S_ * HD_];
__device__ __nv_bfloat16 g_vl[B_ * H_ * S_ * HD_];
__device__ __nv_bfloat16 g_ctx_hi[GM * GK];          // [B,S,D]
__device__ __nv_bfloat16 g_ctx_lo[GM * GK];
// transposed weights [N, K] K-major
__device__ __nv_bfloat16 g_wqt_hi[GN * GK];
__device__ __nv_bfloat16 g_wqt_lo[GN * GK];
__device__ __nv_bfloat16 g_wkt_hi[GN * GK];
__device__ __nv_bfloat16 g_wkt_lo[GN * GK];
__device__ __nv_bfloat16 g_wvt_hi[GN * GK];
__device__ __nv_bfloat16 g_wvt_lo[GN * GK];
__device__ __nv_bfloat16 g_wot_hi[GN * GK];
__device__ __nv_bfloat16 g_wot_lo[GN * GK];

// ---------------------------------------------------------------------------
// Warp-MMA / async-copy primitives
// ---------------------------------------------------------------------------
__device__ __forceinline__ uint32_t smem_u32(const void* p) {
    uint32_t a;
    asm("{ .reg .u64 t; cvta.to.shared.u64 t, %1; cvt.u32.u64 %0, t; }"
        : "=r"(a) : "l"(p));
    return a;
}

__device__ __forceinline__ void mma16816(float* c, const uint32_t* a,
                                         uint32_t b0, uint32_t b1) {
    asm volatile(
        "mma.sync.aligned.m16n8k16.row.col.f32.bf16.bf16.f32 "
        "{%0,%1,%2,%3}, {%4,%5,%6,%7}, {%8,%9}, {%0,%1,%2,%3};"
        : "+f"(c[0]), "+f"(c[1]), "+f"(c[2]), "+f"(c[3])
        : "r"(a[0]), "r"(a[1]), "r"(a[2]), "r"(a[3]), "r"(b0), "r"(b1));
}

__device__ __forceinline__ void ldmx4(uint32_t* r, uint32_t addr) {
    asm volatile("ldmatrix.sync.aligned.m8n8.x4.shared.b16 {%0,%1,%2,%3}, [%4];"
        : "=r"(r[0]), "=r"(r[1]), "=r"(r[2]), "=r"(r[3]) : "r"(addr));
}

__device__ __forceinline__ void ldmx4t(uint32_t* r, uint32_t addr) {
    asm volatile("ldmatrix.sync.aligned.m8n8.x4.trans.shared.b16 {%0,%1,%2,%3}, [%4];"
        : "=r"(r[0]), "=r"(r[1]), "=r"(r[2]), "=r"(r[3]) : "r"(addr));
}

__device__ __forceinline__ void cpa16(uint32_t s, const void* g) {
    asm volatile("cp.async.cg.shared.global [%0], [%1], 16;"
                 :: "r"(s), "l"(g) : "memory");
}
#define CP_COMMIT() asm volatile("cp.async.commit_group;" ::: "memory")
#define CP_WAIT(n)  asm volatile("cp.async.wait_group %0;" :: "n"(n) : "memory")

__device__ __forceinline__ float ex2(float x) {
    float r;
    asm("ex2.approx.f32 %0, %1;" : "=f"(r) : "f"(x));
    return r;
}

__device__ __forceinline__ unsigned pack_hi(float x, float y) {
    __nv_bfloat162 t = __floats2bfloat162_rn(x, y);
    return *reinterpret_cast<unsigned*>(&t);
}
__device__ __forceinline__ unsigned pack_lo(float x, float y) {
    float xr = x - __bfloat162float(__float2bfloat16(x));
    float yr = y - __bfloat162float(__float2bfloat16(y));
    __nv_bfloat162 t = __floats2bfloat162_rn(xr, yr);
    return *reinterpret_cast<unsigned*>(&t);
}
// hi and lo in one go (no redundant hi conversion)
__device__ __forceinline__ void pack_pair(float x, float y, unsigned& hi, unsigned& lo) {
    __nv_bfloat162 h = __floats2bfloat162_rn(x, y);
    hi = *reinterpret_cast<unsigned*>(&h);
    float xr = x - __bfloat162float(h.x);
    float yr = y - __bfloat162float(h.y);
    __nv_bfloat162 l = __floats2bfloat162_rn(xr, yr);
    lo = *reinterpret_cast<unsigned*>(&l);
}

// ---------------------------------------------------------------------------
// GEMM: unchanged from best config (R8/R9): 2-stage, 2 CTAs/SM, term-major.
// MODE 0 epilogue pre-scales Q (z==0) by QSCALE before hi/lo packing.
// ---------------------------------------------------------------------------
#define GP 40                 // smem pitch in bf16 (80 bytes)
#define GT (128 * GP * 2)     // one tile: 10240 bytes
#define GSTAGE (4 * GT)       // one stage (Ah,Al,Bh,Bl): 40960 bytes
#define SMEM_GEMM (2 * GSTAGE)

__device__ __forceinline__ void gemm_issue(uint32_t sb,
    const char* Ah, const char* Al, const char* Bh, const char* Bl,
    int m0, int n0, int c, int t)
{
    int lrow = t >> 1, lq = (t & 1) * 2;
    size_t goA = (size_t)(m0 + lrow) * (GK * 2) + (size_t)c * 64 + lq * 16;
    size_t goB = (size_t)(n0 + lrow) * (GK * 2) + (size_t)c * 64 + lq * 16;
    uint32_t soff = lrow * (GP * 2) + lq * 16;
    cpa16(sb + soff,               Ah + goA);
    cpa16(sb + soff + 16,          Ah + goA + 16);
    cpa16(sb + GT + soff,          Al + goA);
    cpa16(sb + GT + soff + 16,     Al + goA + 16);
    cpa16(sb + 2 * GT + soff,      Bh + goB);
    cpa16(sb + 2 * GT + soff + 16, Bh + goB + 16);
    cpa16(sb + 3 * GT + soff,      Bl + goB);
    cpa16(sb + 3 * GT + soff + 16, Bl + goB + 16);
}

template <int MODE>
__global__ __launch_bounds__(256, 2)
void mma_gemm_kernel(const float* __restrict__ bias, float* __restrict__ dout)
{
    extern __shared__ char smem[];
    const uint32_t sbase = smem_u32(smem);

    const __nv_bfloat16 *Ah, *Al, *Bh, *Bl;
    __nv_bfloat16 *OutH = nullptr, *OutL = nullptr;
    float oscale = 1.0f;
    if (MODE == 0) {
        Ah = g_x_hi; Al = g_x_lo;
        if (blockIdx.z == 0)      { Bh = g_wqt_hi; Bl = g_wqt_lo; OutH = g_qh; OutL = g_ql; oscale = QSCALE; }
        else if (blockIdx.z == 1) { Bh = g_wkt_hi; Bl = g_wkt_lo; OutH = g_kh; OutL = g_kl; }
        else                      { Bh = g_wvt_hi; Bl = g_wvt_lo; OutH = g_vh; OutL = g_vl; }
    } else {
        Ah = g_ctx_hi; Al = g_ctx_lo; Bh = g_wot_hi; Bl = g_wot_lo;
    }

    const int m0   = blockIdx.y * 128;
    const int n0   = blockIdx.x * 128;
    const int t    = threadIdx.x;
    const int lane = t & 31;
    const int wid  = t >> 5;
    const int wm   = wid >> 2;
    const int wn   = wid & 3;

    float acc[4][4][4] = {};

    const int NC = GK / 32;
    gemm_issue(sbase, (const char*)Ah, (const char*)Al,
               (const char*)Bh, (const char*)Bl, m0, n0, 0, t);
    CP_COMMIT();

    for (int c = 0; c < NC; c++) {
        if (c + 1 < NC) {
            gemm_issue(sbase + ((c + 1) & 1) * GSTAGE,
                       (const char*)Ah, (const char*)Al,
                       (const char*)Bh, (const char*)Bl, m0, n0, c + 1, t);
            CP_COMMIT();
            CP_WAIT(1);
        } else {
            CP_WAIT(0);
        }
        __syncthreads();

        const uint32_t sb  = sbase + (c & 1) * GSTAGE;
        const uint32_t uAh = sb,          uAl = sb + GT;
        const uint32_t uBh = sb + 2 * GT, uBl = sb + 3 * GT;

        #pragma unroll
        for (int ks = 0; ks < 2; ks++) {
            uint32_t a_h[4][4], a_l[4][4];
            int abyte = (wm * 64 + (lane & 15)) * (GP * 2) + ks * 32 + (lane >> 4) * 16;
            #pragma unroll
            for (int mt = 0; mt < 4; mt++) {
                ldmx4(a_h[mt], uAh + abyte + mt * 16 * (GP * 2));
                ldmx4(a_l[mt], uAl + abyte + mt * 16 * (GP * 2));
            }
            uint32_t b_h[2][4], b_l[2][4];
            #pragma unroll
            for (int j = 0; j < 2; j++) {
                int bbyte = (wn * 32 + j * 16 + ((lane >> 4) << 3) + (lane & 7)) * (GP * 2)
                          + ks * 32 + ((lane >> 3) & 1) * 16;
                ldmx4(b_h[j], uBh + bbyte);
                ldmx4(b_l[j], uBl + bbyte);
            }
            #pragma unroll
            for (int mt = 0; mt < 4; mt++)
                #pragma unroll
                for (int j = 0; j < 2; j++) {
                    mma16816(acc[mt][2 * j],     a_h[mt], b_h[j][0], b_h[j][1]);
                    mma16816(acc[mt][2 * j + 1], a_h[mt], b_h[j][2], b_h[j][3]);
                }
            #pragma unroll
            for (int mt = 0; mt < 4; mt++)
                #pragma unroll
                for (int j = 0; j < 2; j++) {
                    mma16816(acc[mt][2 * j],     a_h[mt], b_l[j][0], b_l[j][1]);
                    mma16816(acc[mt][2 * j + 1], a_h[mt], b_l[j][2], b_l[j][3]);
                }
            #pragma unroll
            for (int mt = 0; mt < 4; mt++)
                #pragma unroll
                for (int j = 0; j < 2; j++) {
                    mma16816(acc[mt][2 * j],     a_l[mt], b_h[j][0], b_h[j][1]);
                    mma16816(acc[mt][2 * j + 1], a_l[mt], b_h[j][2], b_h[j][3]);
                }
        }
        __syncthreads();
    }

    // Epilogue
    #pragma unroll
    for (int mt = 0; mt < 4; mt++) {
        int mA = m0 + wm * 64 + mt * 16 + (lane >> 2);
        int mB = mA + 8;
        #pragma unroll
        for (int nt = 0; nt < 4; nt++) {
            int n = n0 + wn * 32 + nt * 8 + (lane & 3) * 2;
            float c0 = acc[mt][nt][0], c1 = acc[mt][nt][1];
            float c2 = acc[mt][nt][2], c3 = acc[mt][nt][3];
            if (MODE == 0) {
                c0 *= oscale; c1 *= oscale; c2 *= oscale; c3 *= oscale;
                int h = n >> 6, hd = n & 63;
                {
                    int b = mA >> 11, s = mA & (S_ - 1);
                    size_t o = ((size_t)((b * H_ + h) * S_) + s) * HD_ + hd;
                    unsigned ph, pl;
                    pack_pair(c0, c1, ph, pl);
                    *(unsigned*)&OutH[o] = ph;
                    *(unsigned*)&OutL[o] = pl;
                }
                {
                    int b = mB >> 11, s = mB & (S_ - 1);
                    size_t o = ((size_t)((b * H_ + h) * S_) + s) * HD_ + hd;
                    unsigned ph, pl;
                    pack_pair(c2, c3, ph, pl);
                    *(unsigned*)&OutH[o] = ph;
                    *(unsigned*)&OutL[o] = pl;
                }
            } else {
                float b0 = bias[n], b1 = bias[n + 1];
                *(float2*)&dout[(size_t)mA * GN + n] = make_float2(c0 + b0, c1 + b1);
                *(float2*)&dout[(size_t)mB * GN + n] = make_float2(c2 + b0, c3 + b1);
            }
        }
    }
}

// ---------------------------------------------------------------------------
// Flash attention: warp MMA, causal, split-bf16 3-term.
// 3-stage cp.async ring, ONE __syncthreads per iteration.
// Q loaded gmem->registers directly (no Q smem, no ldmatrix).
// Diagonal-block MMA skipping. exp2-based softmax (scale folded into Q).
// grid (S/64, B*H), 128 threads = 4 warps; warp owns 16 query rows.
// ---------------------------------------------------------------------------
#define AP 72                 // smem pitch in bf16 (144 bytes)
#define AT (64 * AP * 2)      // one tile: 9216 bytes
#define ASTAGE (4 * AT)       // Kh,Kl,Vh,Vl: 36864 bytes
#define SMEM_ATTN (3 * ASTAGE)

__device__ __forceinline__ void attn_issue_kv(uint32_t sb,
    const __nv_bfloat16* Kh, const __nv_bfloat16* Kl,
    const __nv_bfloat16* Vh, const __nv_bfloat16* Vl, int kb, int t)
{
    const uint4* gkh = (const uint4*)(Kh + (size_t)kb * 64 * HD_);
    const uint4* gkl = (const uint4*)(Kl + (size_t)kb * 64 * HD_);
    const uint4* gvh = (const uint4*)(Vh + (size_t)kb * 64 * HD_);
    const uint4* gvl = (const uint4*)(Vl + (size_t)kb * 64 * HD_);
    #pragma unroll
    for (int p = 0; p < 4; p++) {
        int idx = t + p * 128;
        int row = idx >> 3, q = idx & 7;
        uint32_t soff = row * (AP * 2) + q * 16;
        cpa16(sb + soff,          gkh + idx);
        cpa16(sb + AT + soff,     gkl + idx);
        cpa16(sb + 2 * AT + soff, gvh + idx);
        cpa16(sb + 3 * AT + soff, gvl + idx);
    }
}

__global__ __launch_bounds__(128, 2)
void attn_mma_kernel()
{
    extern __shared__ char smem[];
    const uint32_t sbase = smem_u32(smem);

    // heaviest (largest qb) blocks launch first
    const int qb   = gridDim.x - 1 - blockIdx.x;
    const int bh   = blockIdx.y;
    const int t    = threadIdx.x;
    const int lane = t & 31;
    const int wid  = t >> 5;

    const size_t head_off = (size_t)bh * S_ * HD_;
    const __nv_bfloat16* Qh = g_qh + head_off + (size_t)qb * 64 * HD_;
    const __nv_bfloat16* Ql = g_ql + head_off + (size_t)qb * 64 * HD_;
    const __nv_bfloat16* Kh = g_kh + head_off;
    const __nv_bfloat16* Kl = g_kl + head_off;
    const __nv_bfloat16* Vh = g_vh + head_off;
    const __nv_bfloat16* Vl = g_vl + head_off;

    // ---- prefetch kb=0 (stage 0) and kb=1 (stage 1) ----
    attn_issue_kv(sbase, Kh, Kl, Vh, Vl, 0, t);
    CP_COMMIT();
    if (qb >= 1) {
        attn_issue_kv(sbase + ASTAGE, Kh, Kl, Vh, Vl, 1, t);
        CP_COMMIT();
    }

    // ---- Q fragments straight from gmem (mma A-frag layout) ----
    uint32_t aq_h[4][4], aq_l[4][4];
    {
        int r0 = wid * 16 + (lane >> 2);       // rows r0, r0+8
        int c0 = (lane & 3) * 2;               // cols c0, c0+8 within 16-wide slice
        #pragma unroll
        for (int kc = 0; kc < 4; kc++) {
            int base = kc * 16 + c0;
            aq_h[kc][0] = *(const uint32_t*)&Qh[(size_t)r0 * HD_ + base];
            aq_h[kc][1] = *(const uint32_t*)&Qh[(size_t)(r0 + 8) * HD_ + base];
            aq_h[kc][2] = *(const uint32_t*)&Qh[(size_t)r0 * HD_ + base + 8];
            aq_h[kc][3] = *(const uint32_t*)&Qh[(size_t)(r0 + 8) * HD_ + base + 8];
            aq_l[kc][0] = *(const uint32_t*)&Ql[(size_t)r0 * HD_ + base];
            aq_l[kc][1] = *(const uint32_t*)&Ql[(size_t)(r0 + 8) * HD_ + base];
            aq_l[kc][2] = *(const uint32_t*)&Ql[(size_t)r0 * HD_ + base + 8];
            aq_l[kc][3] = *(const uint32_t*)&Ql[(size_t)(r0 + 8) * HD_ + base + 8];
        }
    }

    float oAcc[8][4] = {};
    float m0r = -1e30f, m1r = -1e30f;
    float l0 = 0.0f, l1 = 0.0f;

    for (int kb = 0; kb <= qb; kb++) {
        if (kb + 1 <= qb) { CP_WAIT(1); } else { CP_WAIT(0); }
        __syncthreads();                       // single barrier per iteration
        if (kb + 2 <= qb) {
            attn_issue_kv(sbase + ((kb + 2) % 3) * ASTAGE, Kh, Kl, Vh, Vl, kb + 2, t);
            CP_COMMIT();
        }

        const uint32_t sb  = sbase + (kb % 3) * ASTAGE;
        const uint32_t uKh = sb,          uKl = sb + AT;
        const uint32_t uVh = sb + 2 * AT, uVl = sb + 3 * AT;

        const bool diag = (kb == qb);
        const int  jmax = diag ? wid : 3;      // warp-uniform

        // ---- S = Q K^T (3-term, term-major; skip fully-masked j tiles) ----
        float sc[8][4] = {};
        #pragma unroll
        for (int kc = 0; kc < 4; kc++) {
            uint32_t b_h[4][4], b_l[4][4];
            #pragma unroll
            for (int j = 0; j < 4; j++) {
                if (j <= jmax) {
                    int bbyte = (j * 16 + ((lane >> 4) << 3) + (lane & 7)) * (AP * 2)
                              + kc * 32 + ((lane >> 3) & 1) * 16;
                    ldmx4(b_h[j], uKh + bbyte);
                    ldmx4(b_l[j], uKl + bbyte);
                }
            }
            #pragma unroll
            for (int j = 0; j < 4; j++) {
                if (j <= jmax) {
                    mma16816(sc[2 * j],     aq_h[kc], b_h[j][0], b_h[j][1]);
                    mma16816(sc[2 * j + 1], aq_h[kc], b_h[j][2], b_h[j][3]);
                }
            }
            #pragma unroll
            for (int j = 0; j < 4; j++) {
                if (j <= jmax) {
                    mma16816(sc[2 * j],     aq_h[kc], b_l[j][0], b_l[j][1]);
                    mma16816(sc[2 * j + 1], aq_h[kc], b_l[j][2], b_l[j][3]);
                }
            }
            #pragma unroll
            for (int j = 0; j < 4; j++) {
                if (j <= jmax) {
                    mma16816(sc[2 * j],     aq_l[kc], b_h[j][0], b_h[j][1]);
                    mma16816(sc[2 * j + 1], aq_l[kc], b_h[j][2], b_h[j][3]);
                }
            }
        }

        // ---- causal mask (scores already pre-scaled via Q) ----
        if (diag) {
            int r0l = wid * 16 + (lane >> 2);
            #pragma unroll
            for (int nt = 0; nt < 8; nt++) {
                int col = nt * 8 + (lane & 3) * 2;
                if (col > r0l)         sc[nt][0] = -1e30f;
                if (col + 1 > r0l)     sc[nt][1] = -1e30f;
                if (col > r0l + 8)     sc[nt][2] = -1e30f;
                if (col + 1 > r0l + 8) sc[nt][3] = -1e30f;
            }
        }

        // ---- online softmax in base-2 domain ----
        float mx0 = -1e30f, mx1 = -1e30f;
        #pragma unroll
        for (int nt = 0; nt < 8; nt++) {
            mx0 = fmaxf(mx0, fmaxf(sc[nt][0], sc[nt][1]));
            mx1 = fmaxf(mx1, fmaxf(sc[nt][2], sc[nt][3]));
        }
        mx0 = fmaxf(mx0, __shfl_xor_sync(0xffffffffu, mx0, 1));
        mx0 = fmaxf(mx0, __shfl_xor_sync(0xffffffffu, mx0, 2));
        mx1 = fmaxf(mx1, __shfl_xor_sync(0xffffffffu, mx1, 1));
        mx1 = fmaxf(mx1, __shfl_xor_sync(0xffffffffu, mx1, 2));

        float mn0 = fmaxf(m0r, mx0), mn1 = fmaxf(m1r, mx1);
        float cr0 = ex2(m0r - mn0), cr1 = ex2(m1r - mn1);

        float sum0 = 0.0f, sum1 = 0.0f;
        #pragma unroll
        for (int nt = 0; nt < 8; nt++) {
            float p0 = ex2(sc[nt][0] - mn0);
            float p1 = ex2(sc[nt][1] - mn0);
            float p2 = ex2(sc[nt][2] - mn1);
            float p3 = ex2(sc[nt][3] - mn1);
            sc[nt][0] = p0; sc[nt][1] = p1; sc[nt][2] = p2; sc[nt][3] = p3;
            sum0 += p0 + p1;
            sum1 += p2 + p3;
        }
        sum0 += __shfl_xor_sync(0xffffffffu, sum0, 1);
        sum0 += __shfl_xor_sync(0xffffffffu, sum0, 2);
        sum1 += __shfl_xor_sync(0xffffffffu, sum1, 1);
        sum1 += __shfl_xor_sync(0xffffffffu, sum1, 2);

        l0 = l0 * cr0 + sum0;  m0r = mn0;
        l1 = l1 * cr1 + sum1;  m1r = mn1;

        #pragma unroll
        for (int nt = 0; nt < 8; nt++) {
            oAcc[nt][0] *= cr0; oAcc[nt][1] *= cr0;
            oAcc[nt][2] *= cr1; oAcc[nt][3] *= cr1;
        }

        // ---- O += P V (3-term, term-major; skip zero-P kc tiles on diagonal) ----
        const int kcmax = diag ? wid : 3;      // warp-uniform
        #pragma unroll
        for (int kc = 0; kc < 4; kc++) {
            if (kc > kcmax) break;
            uint32_t pa_h[4], pa_l[4];
            pack_pair(sc[2 * kc][0],     sc[2 * kc][1],     pa_h[0], pa_l[0]);
            pack_pair(sc[2 * kc][2],     sc[2 * kc][3],     pa_h[1], pa_l[1]);
            pack_pair(sc[2 * kc + 1][0], sc[2 * kc + 1][1], pa_h[2], pa_l[2]);
            pack_pair(sc[2 * kc + 1][2], sc[2 * kc + 1][3], pa_h[3], pa_l[3]);
            uint32_t v_h[4][4], v_l[4][4];
            #pragma unroll
            for (int j = 0; j < 4; j++) {
                int key   = kc * 16 + ((lane >> 3) & 1) * 8 + (lane & 7);
                int hd    = j * 16 + (lane >> 4) * 8;
                int vbyte = key * (AP * 2) + hd * 2;
                ldmx4t(v_h[j], uVh + vbyte);
                ldmx4t(v_l[j], uVl + vbyte);
            }
            #pragma unroll
            for (int j = 0; j < 4; j++) {
                mma16816(oAcc[2 * j],     pa_h, v_h[j][0], v_h[j][1]);
                mma16816(oAcc[2 * j + 1], pa_h, v_h[j][2], v_h[j][3]);
            }
            #pragma unroll
            for (int j = 0; j < 4; j++) {
                mma16816(oAcc[2 * j],     pa_h, v_l[j][0], v_l[j][1]);
                mma16816(oAcc[2 * j + 1], pa_h, v_l[j][2], v_l[j][3]);
            }
            #pragma unroll
            for (int j = 0; j < 4; j++) {
                mma16816(oAcc[2 * j],     pa_l, v_h[j][0], v_h[j][1]);
                mma16816(oAcc[2 * j + 1], pa_l, v_h[j][2], v_h[j][3]);
            }
        }
    }

    // ---- finalize: ctx hi/lo bf16 [B,S,D] ----
    const float inv0 = 1.0f / l0, inv1 = 1.0f / l1;
    const int b = bh >> 4, h = bh & 15;
    const int r0 = qb * 64 + wid * 16 + (lane >> 2);
    const int r1 = r0 + 8;
    #pragma unroll
    for (int nt = 0; nt < 8; nt++) {
        int hd = nt * 8 + (lane & 3) * 2;
        float v0 = oAcc[nt][0] * inv0, v1 = oAcc[nt][1] * inv0;
        float v2 = oAcc[nt][2] * inv1, v3 = oAcc[nt][3] * inv1;
        size_t o0 = ((size_t)(b * S_ + r0)) * D_ + h * HD_ + hd;
        size_t o1 = ((size_t)(b * S_ + r1)) * D_ + h * HD_ + hd;
        unsigned ph, pl;
        pack_pair(v0, v1, ph, pl);
        *(unsigned*)&g_ctx_hi[o0] = ph;
        *(unsigned*)&g_ctx_lo[o0] = pl;
        pack_pair(v2, v3, ph, pl);
        *(unsigned*)&g_ctx_hi[o1] = ph;
        *(unsigned*)&g_ctx_lo[o1] = pl;
    }
}

// ---------------------------------------------------------------------------
// fp32 -> (bf16 hi, bf16 lo) split of x
// ---------------------------------------------------------------------------
__global__ void split_x_kernel(const float4* __restrict__ src)
{
    int i = blockIdx.x * blockDim.x + threadIdx.x;
    if (i >= GM * GK / 4) return;
    float4 v = src[i];
    unsigned h0, l0p, h1, l1p;
    pack_pair(v.x, v.y, h0, l0p);
    pack_pair(v.z, v.w, h1, l1p);
    ((unsigned*)g_x_hi)[i * 2]     = h0;
    ((unsigned*)g_x_hi)[i * 2 + 1] = h1;
    ((unsigned*)g_x_lo)[i * 2]     = l0p;
    ((unsigned*)g_x_lo)[i * 2 + 1] = l1p;
}

// ---------------------------------------------------------------------------
// Batched: W [K,N] fp32 -> Wt [N,K] bf16 hi/lo for all 4 weights (blockIdx.z)
// ---------------------------------------------------------------------------
__global__ void transpose_split4_kernel(const float* __restrict__ W0,
                                        const float* __restrict__ W1,
                                        const float* __restrict__ W2,
                                        const float* __restrict__ W3)
{
    __shared__ float tile[32][33];
    const float* W;
    __nv_bfloat16 *hi, *lo;
    switch (blockIdx.z) {
        case 0:  W = W0; hi = g_wqt_hi; lo = g_wqt_lo; break;
        case 1:  W = W1; hi = g_wkt_hi; lo = g_wkt_lo; break;
        case 2:  W = W2; hi = g_wvt_hi; lo = g_wvt_lo; break;
        default: W = W3; hi = g_wot_hi; lo = g_wot_lo; break;
    }
    const int tx = threadIdx.x, ty = threadIdx.y;
    const int k0 = blockIdx.y * 32;
    const int n0 = blockIdx.x * 32;
    #pragma unroll
    for (int j = 0; j < 4; j++)
        tile[ty + j * 8][tx] = W[(size_t)(k0 + ty + j * 8) * GN + n0 + tx];
    __syncthreads();
    #pragma unroll
    for (int j = 0; j < 4; j++) {
        int n = n0 + ty + j * 8;
        int k = k0 + tx;
        float v = tile[tx][ty + j * 8];
        __nv_bfloat16 hv = __float2bfloat16(v);
        hi[(size_t)n * GK + k] = hv;
        lo[(size_t)n * GK + k] = __float2bfloat16(v - __bfloat162float(hv));
    }
}

// ---------------------------------------------------------------------------
extern "C" void kernel_launch(void* const* d_in, const int* in_sizes, int n_in,
                              void* d_out, int out_size)
{
    const float* x  = (const float*)d_in[0];
    const float* Wq = (const float*)d_in[1];
    const float* Wk = (const float*)d_in[2];
    const float* Wv = (const float*)d_in[3];
    const float* Wo = (const float*)d_in[4];
    const float* bo = (const float*)d_in[5];
    float*       out = (float*)d_out;

    cudaFuncSetAttribute(mma_gemm_kernel<0>,
                         cudaFuncAttributeMaxDynamicSharedMemorySize, SMEM_GEMM);
    cudaFuncSetAttribute(mma_gemm_kernel<1>,
                         cudaFuncAttributeMaxDynamicSharedMemorySize, SMEM_GEMM);
    cudaFuncSetAttribute(attn_mma_kernel,
                         cudaFuncAttributeMaxDynamicSharedMemorySize, SMEM_ATTN);

    // 1) prep
    split_x_kernel<<<(GM * GK / 4 + 255) / 256, 256>>>((const float4*)x);
    transpose_split4_kernel<<<dim3(GN / 32, GK / 32, 4), dim3(32, 8)>>>(Wq, Wk, Wv, Wo);

    // 2) QKV projections (Q pre-scaled by QSCALE in epilogue)
    mma_gemm_kernel<0><<<dim3(GN / 128, GM / 128, 3), 256, SMEM_GEMM>>>(nullptr, nullptr);

    // 3) attention (3-stage ring, 1 sync/iter, diag skip, exp2)
    attn_mma_kernel<<<dim3(S_ / 64, B_ * H_), 128, SMEM_ATTN>>>();

    // 4) output projection + bias
    mma_gemm_kernel<1><<<dim3(GN / 128, GM / 128, 1), 256, SMEM_GEMM>>>(bo, out);
}

// round 12
// speedup vs baseline: 1.5465x; 1.5465x over previous
#include <cuda_runtime.h>
#include <cuda_bf16.h>
#include <cuda_fp16.h>
#include <cstdint>

// Problem dims
#define B_  2
#define S_  2048
#define D_  1024
#define H_  16
#define HD_ 64
#define GM  (B_ * S_)   // 4096
#define GN  D_          // 1024
#define GK  D_          // 1024

// softmax scale folded into Q: 1/sqrt(64) * log2(e)
#define QSCALE 0.18033688011112043f

// ---------------------------------------------------------------------------
// Scratch (__device__ globals; allocation-free rule)
// ---------------------------------------------------------------------------
__device__ __nv_bfloat16 g_x_hi[GM * GK];
__device__ __nv_bfloat16 g_x_lo[GM * GK];
__device__ __half g_qh[B_ * H_ * S_ * HD_];   // [B,H,S,HD] fp16 (Q pre-scaled)
__device__ __half g_ql[B_ * H_ * S_ * HD_];
__device__ __half g_kh[B_ * H_ * S_ * HD_];
__device__ __half g_kl[B_ * H_ * S_ * HD_];
__device__ __half g_vh[B_ * H_ * S_ * HD_];
__device__ __half g_vl[B_ * H_ * S_ * HD_];
__device__ __nv_bfloat16 g_ctx_hi[GM * GK];   // [B,S,D] bf16 (feeds out-proj)
__device__ __nv_bfloat16 g_ctx_lo[GM * GK];
// transposed weights [N, K] K-major (bf16)
__device__ __nv_bfloat16 g_wqt_hi[GN * GK];
__device__ __nv_bfloat16 g_wqt_lo[GN * GK];
__device__ __nv_bfloat16 g_wkt_hi[GN * GK];
__device__ __nv_bfloat16 g_wkt_lo[GN * GK];
__device__ __nv_bfloat16 g_wvt_hi[GN * GK];
__device__ __nv_bfloat16 g_wvt_lo[GN * GK];
__device__ __nv_bfloat16 g_wot_hi[GN * GK];
__device__ __nv_bfloat16 g_wot_lo[GN * GK];

// ---------------------------------------------------------------------------
// Warp-MMA / async-copy primitives
// ---------------------------------------------------------------------------
__device__ __forceinline__ uint32_t smem_u32(const void* p) {
    uint32_t a;
    asm("{ .reg .u64 t; cvta.to.shared.u64 t, %1; cvt.u32.u64 %0, t; }"
        : "=r"(a) : "l"(p));
    return a;
}

// bf16 in, f32 acc
__device__ __forceinline__ void mma16816(float* c, const uint32_t* a,
                                         uint32_t b0, uint32_t b1) {
    asm volatile(
        "mma.sync.aligned.m16n8k16.row.col.f32.bf16.bf16.f32 "
        "{%0,%1,%2,%3}, {%4,%5,%6,%7}, {%8,%9}, {%0,%1,%2,%3};"
        : "+f"(c[0]), "+f"(c[1]), "+f"(c[2]), "+f"(c[3])
        : "r"(a[0]), "r"(a[1]), "r"(a[2]), "r"(a[3]), "r"(b0), "r"(b1));
}

// fp16 in, f32 acc
__device__ __forceinline__ void mma16816h(float* c, const uint32_t* a,
                                          uint32_t b0, uint32_t b1) {
    asm volatile(
        "mma.sync.aligned.m16n8k16.row.col.f32.f16.f16.f32 "
        "{%0,%1,%2,%3}, {%4,%5,%6,%7}, {%8,%9}, {%0,%1,%2,%3};"
        : "+f"(c[0]), "+f"(c[1]), "+f"(c[2]), "+f"(c[3])
        : "r"(a[0]), "r"(a[1]), "r"(a[2]), "r"(a[3]), "r"(b0), "r"(b1));
}

// fp16 in, f16 acc (2 packed regs) — potential 2x-rate pipe
__device__ __forceinline__ void mma16816hh(uint32_t* c, const uint32_t* a,
                                           uint32_t b0, uint32_t b1) {
    asm volatile(
        "mma.sync.aligned.m16n8k16.row.col.f16.f16.f16.f16 "
        "{%0,%1}, {%2,%3,%4,%5}, {%6,%7}, {%0,%1};"
        : "+r"(c[0]), "+r"(c[1])
        : "r"(a[0]), "r"(a[1]), "r"(a[2]), "r"(a[3]), "r"(b0), "r"(b1));
}

__device__ __forceinline__ void ldmx4(uint32_t* r, uint32_t addr) {
    asm volatile("ldmatrix.sync.aligned.m8n8.x4.shared.b16 {%0,%1,%2,%3}, [%4];"
        : "=r"(r[0]), "=r"(r[1]), "=r"(r[2]), "=r"(r[3]) : "r"(addr));
}

__device__ __forceinline__ void ldmx4t(uint32_t* r, uint32_t addr) {
    asm volatile("ldmatrix.sync.aligned.m8n8.x4.trans.shared.b16 {%0,%1,%2,%3}, [%4];"
        : "=r"(r[0]), "=r"(r[1]), "=r"(r[2]), "=r"(r[3]) : "r"(addr));
}

__device__ __forceinline__ void cpa16(uint32_t s, const void* g) {
    asm volatile("cp.async.cg.shared.global [%0], [%1], 16;"
                 :: "r"(s), "l"(g) : "memory");
}
#define CP_COMMIT() asm volatile("cp.async.commit_group;" ::: "memory")
#define CP_WAIT(n)  asm volatile("cp.async.wait_group %0;" :: "n"(n) : "memory")

__device__ __forceinline__ float ex2(float x) {
    float r;
    asm("ex2.approx.f32 %0, %1;" : "=f"(r) : "f"(x));
    return r;
}

// bf16 hi/lo pack
__device__ __forceinline__ void pack_pair_bf(float x, float y, unsigned& hi, unsigned& lo) {
    __nv_bfloat162 h = __floats2bfloat162_rn(x, y);
    hi = *reinterpret_cast<unsigned*>(&h);
    float xr = x - __bfloat162float(h.x);
    float yr = y - __bfloat162float(h.y);
    __nv_bfloat162 l = __floats2bfloat162_rn(xr, yr);
    lo = *reinterpret_cast<unsigned*>(&l);
}
// fp16 hi/lo pack
__device__ __forceinline__ void pack_pair_h(float x, float y, unsigned& hi, unsigned& lo) {
    __half2 h = __floats2half2_rn(x, y);
    hi = *reinterpret_cast<unsigned*>(&h);
    float xr = x - __half2float(__low2half(h));
    float yr = y - __half2float(__high2half(h));
    __half2 l = __floats2half2_rn(xr, yr);
    lo = *reinterpret_cast<unsigned*>(&l);
}

// ---------------------------------------------------------------------------
// GEMM (identical to R9 best): 2-stage cp.async, 2 CTAs/SM, term-major bf16.
// MODE 0: out -> fp16 hi/lo [B,H,S,HD]; Q (z==0) pre-scaled by QSCALE.
// MODE 1: A = ctx (bf16), B = Wo; out -> fp32 [M,N] + bias
// ---------------------------------------------------------------------------
#define GP 40                 // smem pitch in bf16 (80 bytes)
#define GT (128 * GP * 2)     // one tile: 10240 bytes
#define GSTAGE (4 * GT)       // one stage (Ah,Al,Bh,Bl): 40960 bytes
#define SMEM_GEMM (2 * GSTAGE)

__device__ __forceinline__ void gemm_issue(uint32_t sb,
    const char* Ah, const char* Al, const char* Bh, const char* Bl,
    int m0, int n0, int c, int t)
{
    int lrow = t >> 1, lq = (t & 1) * 2;
    size_t goA = (size_t)(m0 + lrow) * (GK * 2) + (size_t)c * 64 + lq * 16;
    size_t goB = (size_t)(n0 + lrow) * (GK * 2) + (size_t)c * 64 + lq * 16;
    uint32_t soff = lrow * (GP * 2) + lq * 16;
    cpa16(sb + soff,               Ah + goA);
    cpa16(sb + soff + 16,          Ah + goA + 16);
    cpa16(sb + GT + soff,          Al + goA);
    cpa16(sb + GT + soff + 16,     Al + goA + 16);
    cpa16(sb + 2 * GT + soff,      Bh + goB);
    cpa16(sb + 2 * GT + soff + 16, Bh + goB + 16);
    cpa16(sb + 3 * GT + soff,      Bl + goB);
    cpa16(sb + 3 * GT + soff + 16, Bl + goB + 16);
}

template <int MODE>
__global__ __launch_bounds__(256, 2)
void mma_gemm_kernel(const float* __restrict__ bias, float* __restrict__ dout)
{
    extern __shared__ char smem[];
    const uint32_t sbase = smem_u32(smem);

    const __nv_bfloat16 *Ah, *Al, *Bh, *Bl;
    __half *OutH = nullptr, *OutL = nullptr;
    float oscale = 1.0f;
    if (MODE == 0) {
        Ah = g_x_hi; Al = g_x_lo;
        if (blockIdx.z == 0)      { Bh = g_wqt_hi; Bl = g_wqt_lo; OutH = g_qh; OutL = g_ql; oscale = QSCALE; }
        else if (blockIdx.z == 1) { Bh = g_wkt_hi; Bl = g_wkt_lo; OutH = g_kh; OutL = g_kl; }
        else                      { Bh = g_wvt_hi; Bl = g_wvt_lo; OutH = g_vh; OutL = g_vl; }
    } else {
        Ah = g_ctx_hi; Al = g_ctx_lo; Bh = g_wot_hi; Bl = g_wot_lo;
    }

    const int m0   = blockIdx.y * 128;
    const int n0   = blockIdx.x * 128;
    const int t    = threadIdx.x;
    const int lane = t & 31;
    const int wid  = t >> 5;
    const int wm   = wid >> 2;
    const int wn   = wid & 3;

    float acc[4][4][4] = {};

    const int NC = GK / 32;
    gemm_issue(sbase, (const char*)Ah, (const char*)Al,
               (const char*)Bh, (const char*)Bl, m0, n0, 0, t);
    CP_COMMIT();

    for (int c = 0; c < NC; c++) {
        if (c + 1 < NC) {
            gemm_issue(sbase + ((c + 1) & 1) * GSTAGE,
                       (const char*)Ah, (const char*)Al,
                       (const char*)Bh, (const char*)Bl, m0, n0, c + 1, t);
            CP_COMMIT();
            CP_WAIT(1);
        } else {
            CP_WAIT(0);
        }
        __syncthreads();

        const uint32_t sb  = sbase + (c & 1) * GSTAGE;
        const uint32_t uAh = sb,          uAl = sb + GT;
        const uint32_t uBh = sb + 2 * GT, uBl = sb + 3 * GT;

        #pragma unroll
        for (int ks = 0; ks < 2; ks++) {
            uint32_t a_h[4][4], a_l[4][4];
            int abyte = (wm * 64 + (lane & 15)) * (GP * 2) + ks * 32 + (lane >> 4) * 16;
            #pragma unroll
            for (int mt = 0; mt < 4; mt++) {
                ldmx4(a_h[mt], uAh + abyte + mt * 16 * (GP * 2));
                ldmx4(a_l[mt], uAl + abyte + mt * 16 * (GP * 2));
            }
            uint32_t b_h[2][4], b_l[2][4];
            #pragma unroll
            for (int j = 0; j < 2; j++) {
                int bbyte = (wn * 32 + j * 16 + ((lane >> 4) << 3) + (lane & 7)) * (GP * 2)
                          + ks * 32 + ((lane >> 3) & 1) * 16;
                ldmx4(b_h[j], uBh + bbyte);
                ldmx4(b_l[j], uBl + bbyte);
            }
            #pragma unroll
            for (int mt = 0; mt < 4; mt++)
                #pragma unroll
                for (int j = 0; j < 2; j++) {
                    mma16816(acc[mt][2 * j],     a_h[mt], b_h[j][0], b_h[j][1]);
                    mma16816(acc[mt][2 * j + 1], a_h[mt], b_h[j][2], b_h[j][3]);
                }
            #pragma unroll
            for (int mt = 0; mt < 4; mt++)
                #pragma unroll
                for (int j = 0; j < 2; j++) {
                    mma16816(acc[mt][2 * j],     a_h[mt], b_l[j][0], b_l[j][1]);
                    mma16816(acc[mt][2 * j + 1], a_h[mt], b_l[j][2], b_l[j][3]);
                }
            #pragma unroll
            for (int mt = 0; mt < 4; mt++)
                #pragma unroll
                for (int j = 0; j < 2; j++) {
                    mma16816(acc[mt][2 * j],     a_l[mt], b_h[j][0], b_h[j][1]);
                    mma16816(acc[mt][2 * j + 1], a_l[mt], b_h[j][2], b_h[j][3]);
                }
        }
        __syncthreads();
    }

    // Epilogue
    #pragma unroll
    for (int mt = 0; mt < 4; mt++) {
        int mA = m0 + wm * 64 + mt * 16 + (lane >> 2);
        int mB = mA + 8;
        #pragma unroll
        for (int nt = 0; nt < 4; nt++) {
            int n = n0 + wn * 32 + nt * 8 + (lane & 3) * 2;
            float c0 = acc[mt][nt][0], c1 = acc[mt][nt][1];
            float c2 = acc[mt][nt][2], c3 = acc[mt][nt][3];
            if (MODE == 0) {
                c0 *= oscale; c1 *= oscale; c2 *= oscale; c3 *= oscale;
                int h = n >> 6, hd = n & 63;
                {
                    int b = mA >> 11, s = mA & (S_ - 1);
                    size_t o = ((size_t)((b * H_ + h) * S_) + s) * HD_ + hd;
                    unsigned ph, pl;
                    pack_pair_h(c0, c1, ph, pl);
                    *(unsigned*)&OutH[o] = ph;
                    *(unsigned*)&OutL[o] = pl;
                }
                {
                    int b = mB >> 11, s = mB & (S_ - 1);
                    size_t o = ((size_t)((b * H_ + h) * S_) + s) * HD_ + hd;
                    unsigned ph, pl;
                    pack_pair_h(c2, c3, ph, pl);
                    *(unsigned*)&OutH[o] = ph;
                    *(unsigned*)&OutL[o] = pl;
                }
            } else {
                float b0 = bias[n], b1 = bias[n + 1];
                *(float2*)&dout[(size_t)mA * GN + n] = make_float2(c0 + b0, c1 + b1);
                *(float2*)&dout[(size_t)mB * GN + n] = make_float2(c2 + b0, c3 + b1);
            }
        }
    }
}

// ---------------------------------------------------------------------------
// Flash attention (R9 structure): fp16 split, causal, 2-stage cp.async.
// Main terms f32-acc, cross terms f16-acc (merged per block).
// grid (S/64, B*H), 128 threads = 4 warps; warp owns 16 query rows.
// ---------------------------------------------------------------------------
#define AP 72                 // smem pitch in fp16 (144 bytes)
#define AT (64 * AP * 2)      // one tile: 9216 bytes
#define ASTAGE (4 * AT)       // Kh,Kl,Vh,Vl: 36864 bytes
#define SMEM_ATTN (2 * ASTAGE)

__device__ __forceinline__ void attn_issue_kv(uint32_t sb,
    const __half* Kh, const __half* Kl,
    const __half* Vh, const __half* Vl, int kb, int t)
{
    const uint4* gkh = (const uint4*)(Kh + (size_t)kb * 64 * HD_);
    const uint4* gkl = (const uint4*)(Kl + (size_t)kb * 64 * HD_);
    const uint4* gvh = (const uint4*)(Vh + (size_t)kb * 64 * HD_);
    const uint4* gvl = (const uint4*)(Vl + (size_t)kb * 64 * HD_);
    #pragma unroll
    for (int p = 0; p < 4; p++) {
        int idx = t + p * 128;
        int row = idx >> 3, q = idx & 7;
        uint32_t soff = row * (AP * 2) + q * 16;
        cpa16(sb + soff,          gkh + idx);
        cpa16(sb + AT + soff,     gkl + idx);
        cpa16(sb + 2 * AT + soff, gvh + idx);
        cpa16(sb + 3 * AT + soff, gvl + idx);
    }
}

__global__ __launch_bounds__(128, 2)
void attn_mma_kernel()
{
    extern __shared__ char smem[];
    const uint32_t sbase = smem_u32(smem);

    // heaviest (largest qb) blocks launch first
    const int qb   = gridDim.x - 1 - blockIdx.x;
    const int bh   = blockIdx.y;
    const int t    = threadIdx.x;
    const int lane = t & 31;
    const int wid  = t >> 5;

    const size_t head_off = (size_t)bh * S_ * HD_;
    const __half* Qh = g_qh + head_off + (size_t)qb * 64 * HD_;
    const __half* Ql = g_ql + head_off + (size_t)qb * 64 * HD_;
    const __half* Kh = g_kh + head_off;
    const __half* Kl = g_kl + head_off;
    const __half* Vh = g_vh + head_off;
    const __half* Vl = g_vl + head_off;

    // ---- stage Q into stage-1 K buffers via cp.async (group 0) ----
    {
        uint32_t qsb = sbase + ASTAGE;
        #pragma unroll
        for (int p = 0; p < 4; p++) {
            int idx = t + p * 128;
            int row = idx >> 3, q = idx & 7;
            uint32_t soff = row * (AP * 2) + q * 16;
            cpa16(qsb + soff,      ((const uint4*)Qh) + idx);
            cpa16(qsb + AT + soff, ((const uint4*)Ql) + idx);
        }
        CP_COMMIT();
    }
    // ---- kb=0 K/V into stage 0 (group 1) ----
    attn_issue_kv(sbase, Kh, Kl, Vh, Vl, 0, t);
    CP_COMMIT();

    CP_WAIT(1);
    __syncthreads();

    uint32_t aq_h[4][4], aq_l[4][4];
    {
        uint32_t uQh = sbase + ASTAGE, uQl = sbase + ASTAGE + AT;
        int qbyte = (wid * 16 + (lane & 15)) * (AP * 2) + (lane >> 4) * 16;
        #pragma unroll
        for (int kc = 0; kc < 4; kc++) {
            ldmx4(aq_h[kc], uQh + qbyte + kc * 32);
            ldmx4(aq_l[kc], uQl + qbyte + kc * 32);
        }
    }
    __syncthreads();

    float oAcc[8][4] = {};
    float m0r = -1e30f, m1r = -1e30f;
    float l0 = 0.0f, l1 = 0.0f;

    for (int kb = 0; kb <= qb; kb++) {
        if (kb < qb) {
            attn_issue_kv(sbase + ((kb + 1) & 1) * ASTAGE, Kh, Kl, Vh, Vl, kb + 1, t);
            CP_COMMIT();
            CP_WAIT(1);
        } else {
            CP_WAIT(0);
        }
        __syncthreads();

        const uint32_t sb  = sbase + (kb & 1) * ASTAGE;
        const uint32_t uKh = sb,          uKl = sb + AT;
        const uint32_t uVh = sb + 2 * AT, uVl = sb + 3 * AT;

        // ---- S = Q K^T: main f32-acc; crosses into shared f16-acc ----
        float sc[8][4] = {};
        uint32_t cx[8][2];
        #pragma unroll
        for (int nt = 0; nt < 8; nt++) { cx[nt][0] = 0u; cx[nt][1] = 0u; }

        #pragma unroll
        for (int kc = 0; kc < 4; kc++) {
            uint32_t b_h[4][4], b_l[4][4];
            #pragma unroll
            for (int j = 0; j < 4; j++) {
                int bbyte = (j * 16 + ((lane >> 4) << 3) + (lane & 7)) * (AP * 2)
                          + kc * 32 + ((lane >> 3) & 1) * 16;
                ldmx4(b_h[j], uKh + bbyte);
                ldmx4(b_l[j], uKl + bbyte);
            }
            #pragma unroll
            for (int j = 0; j < 4; j++) {
                mma16816h(sc[2 * j],     aq_h[kc], b_h[j][0], b_h[j][1]);
                mma16816h(sc[2 * j + 1], aq_h[kc], b_h[j][2], b_h[j][3]);
            }
            #pragma unroll
            for (int j = 0; j < 4; j++) {
                mma16816hh(&cx[2 * j][0],     aq_h[kc], b_l[j][0], b_l[j][1]);
                mma16816hh(&cx[2 * j + 1][0], aq_h[kc], b_l[j][2], b_l[j][3]);
            }
            #pragma unroll
            for (int j = 0; j < 4; j++) {
                mma16816hh(&cx[2 * j][0],     aq_l[kc], b_h[j][0], b_h[j][1]);
                mma16816hh(&cx[2 * j + 1][0], aq_l[kc], b_h[j][2], b_h[j][3]);
            }
        }
        // merge f16 cross sums into f32 scores
        #pragma unroll
        for (int nt = 0; nt < 8; nt++) {
            __half2 h0 = *reinterpret_cast<__half2*>(&cx[nt][0]);
            __half2 h1 = *reinterpret_cast<__half2*>(&cx[nt][1]);
            sc[nt][0] += __low2float(h0);  sc[nt][1] += __high2float(h0);
            sc[nt][2] += __low2float(h1);  sc[nt][3] += __high2float(h1);
        }

        // ---- causal mask (scores pre-scaled via Q; log2 domain) ----
        if (kb == qb) {
            int r0l = wid * 16 + (lane >> 2);
            #pragma unroll
            for (int nt = 0; nt < 8; nt++) {
                int col = nt * 8 + (lane & 3) * 2;
                if (col > r0l)         sc[nt][0] = -1e30f;
                if (col + 1 > r0l)     sc[nt][1] = -1e30f;
                if (col > r0l + 8)     sc[nt][2] = -1e30f;
                if (col + 1 > r0l + 8) sc[nt][3] = -1e30f;
            }
        }

        // ---- online softmax (base-2) ----
        float mx0 = -1e30f, mx1 = -1e30f;
        #pragma unroll
        for (int nt = 0; nt < 8; nt++) {
            mx0 = fmaxf(mx0, fmaxf(sc[nt][0], sc[nt][1]));
            mx1 = fmaxf(mx1, fmaxf(sc[nt][2], sc[nt][3]));
        }
        mx0 = fmaxf(mx0, __shfl_xor_sync(0xffffffffu, mx0, 1));
        mx0 = fmaxf(mx0, __shfl_xor_sync(0xffffffffu, mx0, 2));
        mx1 = fmaxf(mx1, __shfl_xor_sync(0xffffffffu, mx1, 1));
        mx1 = fmaxf(mx1, __shfl_xor_sync(0xffffffffu, mx1, 2));

        float mn0 = fmaxf(m0r, mx0), mn1 = fmaxf(m1r, mx1);
        float cr0 = ex2(m0r - mn0), cr1 = ex2(m1r - mn1);

        float sum0 = 0.0f, sum1 = 0.0f;
        #pragma unroll
        for (int nt = 0; nt < 8; nt++) {
            float p0 = ex2(sc[nt][0] - mn0);
            float p1 = ex2(sc[nt][1] - mn0);
            float p2 = ex2(sc[nt][2] - mn1);
            float p3 = ex2(sc[nt][3] - mn1);
            sc[nt][0] = p0; sc[nt][1] = p1; sc[nt][2] = p2; sc[nt][3] = p3;
            sum0 += p0 + p1;
            sum1 += p2 + p3;
        }
        sum0 += __shfl_xor_sync(0xffffffffu, sum0, 1);
        sum0 += __shfl_xor_sync(0xffffffffu, sum0, 2);
        sum1 += __shfl_xor_sync(0xffffffffu, sum1, 1);
        sum1 += __shfl_xor_sync(0xffffffffu, sum1, 2);

        l0 = l0 * cr0 + sum0;  m0r = mn0;
        l1 = l1 * cr1 + sum1;  m1r = mn1;

        #pragma unroll
        for (int nt = 0; nt < 8; nt++) {
            oAcc[nt][0] *= cr0; oAcc[nt][1] *= cr0;
            oAcc[nt][2] *= cr1; oAcc[nt][3] *= cr1;
        }

        // ---- O += P V: main f32-acc; crosses into f16-acc, merged per block ----
        uint32_t ox[8][2];
        #pragma unroll
        for (int nt = 0; nt < 8; nt++) { ox[nt][0] = 0u; ox[nt][1] = 0u; }

        #pragma unroll
        for (int kc = 0; kc < 4; kc++) {
            uint32_t pa_h[4], pa_l[4];
            pack_pair_h(sc[2 * kc][0],     sc[2 * kc][1],     pa_h[0], pa_l[0]);
            pack_pair_h(sc[2 * kc][2],     sc[2 * kc][3],     pa_h[1], pa_l[1]);
            pack_pair_h(sc[2 * kc + 1][0], sc[2 * kc + 1][1], pa_h[2], pa_l[2]);
            pack_pair_h(sc[2 * kc + 1][2], sc[2 * kc + 1][3], pa_h[3], pa_l[3]);
            uint32_t v_h[4][4], v_l[4][4];
            #pragma unroll
            for (int j = 0; j < 4; j++) {
                int key   = kc * 16 + ((lane >> 3) & 1) * 8 + (lane & 7);
                int hd    = j * 16 + (lane >> 4) * 8;
                int vbyte = key * (AP * 2) + hd * 2;
                ldmx4t(v_h[j], uVh + vbyte);
                ldmx4t(v_l[j], uVl + vbyte);
            }
            #pragma unroll
            for (int j = 0; j < 4; j++) {
                mma16816h(oAcc[2 * j],     pa_h, v_h[j][0], v_h[j][1]);
                mma16816h(oAcc[2 * j + 1], pa_h, v_h[j][2], v_h[j][3]);
            }
            #pragma unroll
            for (int j = 0; j < 4; j++) {
                mma16816hh(&ox[2 * j][0],     pa_h, v_l[j][0], v_l[j][1]);
                mma16816hh(&ox[2 * j + 1][0], pa_h, v_l[j][2], v_l[j][3]);
            }
            #pragma unroll
            for (int j = 0; j < 4; j++) {
                mma16816hh(&ox[2 * j][0],     pa_l, v_h[j][0], v_h[j][1]);
                mma16816hh(&ox[2 * j + 1][0], pa_l, v_h[j][2], v_h[j][3]);
            }
        }
        // merge f16 cross sums into f32 output accumulators
        #pragma unroll
        for (int nt = 0; nt < 8; nt++) {
            __half2 h0 = *reinterpret_cast<__half2*>(&ox[nt][0]);
            __half2 h1 = *reinterpret_cast<__half2*>(&ox[nt][1]);
            oAcc[nt][0] += __low2float(h0);  oAcc[nt][1] += __high2float(h0);
            oAcc[nt][2] += __low2float(h1);  oAcc[nt][3] += __high2float(h1);
        }
        __syncthreads();
    }

    // ---- finalize: ctx hi/lo bf16 [B,S,D] ----
    const float inv0 = 1.0f / l0, inv1 = 1.0f / l1;
    const int b = bh >> 4, h = bh & 15;
    const int r0 = qb * 64 + wid * 16 + (lane >> 2);
    const int r1 = r0 + 8;
    #pragma unroll
    for (int nt = 0; nt < 8; nt++) {
        int hd = nt * 8 + (lane & 3) * 2;
        float v0 = oAcc[nt][0] * inv0, v1 = oAcc[nt][1] * inv0;
        float v2 = oAcc[nt][2] * inv1, v3 = oAcc[nt][3] * inv1;
        size_t o0 = ((size_t)(b * S_ + r0)) * D_ + h * HD_ + hd;
        size_t o1 = ((size_t)(b * S_ + r1)) * D_ + h * HD_ + hd;
        unsigned ph, pl;
        pack_pair_bf(v0, v1, ph, pl);
        *(unsigned*)&g_ctx_hi[o0] = ph;
        *(unsigned*)&g_ctx_lo[o0] = pl;
        pack_pair_bf(v2, v3, ph, pl);
        *(unsigned*)&g_ctx_hi[o1] = ph;
        *(unsigned*)&g_ctx_lo[o1] = pl;
    }
}

// ---------------------------------------------------------------------------
// fp32 -> (bf16 hi, bf16 lo) split of x
// ---------------------------------------------------------------------------
__global__ void split_x_kernel(const float4* __restrict__ src)
{
    int i = blockIdx.x * blockDim.x + threadIdx.x;
    if (i >= GM * GK / 4) return;
    float4 v = src[i];
    unsigned h0, l0p, h1, l1p;
    pack_pair_bf(v.x, v.y, h0, l0p);
    pack_pair_bf(v.z, v.w, h1, l1p);
    ((unsigned*)g_x_hi)[i * 2]     = h0;
    ((unsigned*)g_x_hi)[i * 2 + 1] = h1;
    ((unsigned*)g_x_lo)[i * 2]     = l0p;
    ((unsigned*)g_x_lo)[i * 2 + 1] = l1p;
}

// ---------------------------------------------------------------------------
// Batched: W [K,N] fp32 -> Wt [N,K] bf16 hi/lo for all 4 weights (blockIdx.z)
// ---------------------------------------------------------------------------
__global__ void transpose_split4_kernel(const float* __restrict__ W0,
                                        const float* __restrict__ W1,
                                        const float* __restrict__ W2,
                                        const float* __restrict__ W3)
{
    __shared__ float tile[32][33];
    const float* W;
    __nv_bfloat16 *hi, *lo;
    switch (blockIdx.z) {
        case 0:  W = W0; hi = g_wqt_hi; lo = g_wqt_lo; break;
        case 1:  W = W1; hi = g_wkt_hi; lo = g_wkt_lo; break;
        case 2:  W = W2; hi = g_wvt_hi; lo = g_wvt_lo; break;
        default: W = W3; hi = g_wot_hi; lo = g_wot_lo; break;
    }
    const int tx = threadIdx.x, ty = threadIdx.y;
    const int k0 = blockIdx.y * 32;
    const int n0 = blockIdx.x * 32;
    #pragma unroll
    for (int j = 0; j < 4; j++)
        tile[ty + j * 8][tx] = W[(size_t)(k0 + ty + j * 8) * GN + n0 + tx];
    __syncthreads();
    #pragma unroll
    for (int j = 0; j < 4; j++) {
        int n = n0 + ty + j * 8;
        int k = k0 + tx;
        float v = tile[tx][ty + j * 8];
        __nv_bfloat16 hv = __float2bfloat16(v);
        hi[(size_t)n * GK + k] = hv;
        lo[(size_t)n * GK + k] = __float2bfloat16(v - __bfloat162float(hv));
    }
}

// ---------------------------------------------------------------------------
extern "C" void kernel_launch(void* const* d_in, const int* in_sizes, int n_in,
                              void* d_out, int out_size)
{
    const float* x  = (const float*)d_in[0];
    const float* Wq = (const float*)d_in[1];
    const float* Wk = (const float*)d_in[2];
    const float* Wv = (const float*)d_in[3];
    const float* Wo = (const float*)d_in[4];
    const float* bo = (const float*)d_in[5];
    float*       out = (float*)d_out;

    cudaFuncSetAttribute(mma_gemm_kernel<0>,
                         cudaFuncAttributeMaxDynamicSharedMemorySize, SMEM_GEMM);
    cudaFuncSetAttribute(mma_gemm_kernel<1>,
                         cudaFuncAttributeMaxDynamicSharedMemorySize, SMEM_GEMM);
    cudaFuncSetAttribute(attn_mma_kernel,
                         cudaFuncAttributeMaxDynamicSharedMemorySize, SMEM_ATTN);

    // 1) prep
    split_x_kernel<<<(GM * GK / 4 + 255) / 256, 256>>>((const float4*)x);
    transpose_split4_kernel<<<dim3(GN / 32, GK / 32, 4), dim3(32, 8)>>>(Wq, Wk, Wv, Wo);

    // 2) QKV projections -> fp16 hi/lo (Q pre-scaled by QSCALE)
    mma_gemm_kernel<0><<<dim3(GN / 128, GM / 128, 3), 256, SMEM_GEMM>>>(nullptr, nullptr);

    // 3) attention (fp16, f16-acc cross terms) -> ctx bf16 hi/lo
    attn_mma_kernel<<<dim3(S_ / 64, B_ * H_), 128, SMEM_ATTN>>>();

    // 4) output projection + bias -> fp32 out
    mma_gemm_kernel<1><<<dim3(GN / 128, GM / 128, 1), 256, SMEM_GEMM>>>(bo, out);
}

// round 13
// speedup vs baseline: 2.2339x; 1.4444x over previous
#include <cuda_runtime.h>
#include <cuda_bf16.h>
#include <cuda_fp16.h>
#include <cstdint>

// Problem dims
#define B_  2
#define S_  2048
#define D_  1024
#define H_  16
#define HD_ 64
#define GM  (B_ * S_)   // 4096
#define GN  D_          // 1024
#define GK  D_          // 1024

// softmax scale folded into Q: 1/sqrt(64) * log2(e)
#define QSCALE 0.18033688011112043f

// ---------------------------------------------------------------------------
// Scratch (__device__ globals; allocation-free rule) — all fp16 now
// ---------------------------------------------------------------------------
__device__ __half g_x_hi[GM * GK];
__device__ __half g_x_lo[GM * GK];
__device__ __half g_qh[B_ * H_ * S_ * HD_];   // [B,H,S,HD] (Q pre-scaled)
__device__ __half g_ql[B_ * H_ * S_ * HD_];
__device__ __half g_kh[B_ * H_ * S_ * HD_];   // K single fp16
__device__ __half g_vh[B_ * H_ * S_ * HD_];   // V single fp16
__device__ __half g_ctx_hi[GM * GK];          // [B,S,D]
__device__ __half g_ctx_lo[GM * GK];
// transposed weights [N, K] K-major, single fp16
__device__ __half g_wqt[GN * GK];
__device__ __half g_wkt[GN * GK];
__device__ __half g_wvt[GN * GK];
__device__ __half g_wot[GN * GK];

// ---------------------------------------------------------------------------
// Warp-MMA / async-copy primitives
// ---------------------------------------------------------------------------
__device__ __forceinline__ uint32_t smem_u32(const void* p) {
    uint32_t a;
    asm("{ .reg .u64 t; cvta.to.shared.u64 t, %1; cvt.u32.u64 %0, t; }"
        : "=r"(a) : "l"(p));
    return a;
}

// fp16 in, f32 acc
__device__ __forceinline__ void mma16816h(float* c, const uint32_t* a,
                                          uint32_t b0, uint32_t b1) {
    asm volatile(
        "mma.sync.aligned.m16n8k16.row.col.f32.f16.f16.f32 "
        "{%0,%1,%2,%3}, {%4,%5,%6,%7}, {%8,%9}, {%0,%1,%2,%3};"
        : "+f"(c[0]), "+f"(c[1]), "+f"(c[2]), "+f"(c[3])
        : "r"(a[0]), "r"(a[1]), "r"(a[2]), "r"(a[3]), "r"(b0), "r"(b1));
}

__device__ __forceinline__ void ldmx4(uint32_t* r, uint32_t addr) {
    asm volatile("ldmatrix.sync.aligned.m8n8.x4.shared.b16 {%0,%1,%2,%3}, [%4];"
        : "=r"(r[0]), "=r"(r[1]), "=r"(r[2]), "=r"(r[3]) : "r"(addr));
}

__device__ __forceinline__ void ldmx4t(uint32_t* r, uint32_t addr) {
    asm volatile("ldmatrix.sync.aligned.m8n8.x4.trans.shared.b16 {%0,%1,%2,%3}, [%4];"
        : "=r"(r[0]), "=r"(r[1]), "=r"(r[2]), "=r"(r[3]) : "r"(addr));
}

__device__ __forceinline__ void cpa16(uint32_t s, const void* g) {
    asm volatile("cp.async.cg.shared.global [%0], [%1], 16;"
                 :: "r"(s), "l"(g) : "memory");
}
#define CP_COMMIT() asm volatile("cp.async.commit_group;" ::: "memory")
#define CP_WAIT(n)  asm volatile("cp.async.wait_group %0;" :: "n"(n) : "memory")

__device__ __forceinline__ float ex2(float x) {
    float r;
    asm("ex2.approx.f32 %0, %1;" : "=f"(r) : "f"(x));
    return r;
}

// fp16 hi/lo pack
__device__ __forceinline__ void pack_pair_h(float x, float y, unsigned& hi, unsigned& lo) {
    __half2 h = __floats2half2_rn(x, y);
    hi = *reinterpret_cast<unsigned*>(&h);
    float xr = x - __half2float(__low2half(h));
    float yr = y - __half2float(__high2half(h));
    __half2 l = __floats2half2_rn(xr, yr);
    lo = *reinterpret_cast<unsigned*>(&l);
}

// ---------------------------------------------------------------------------
// GEMM: C[128,128] tile of A[M,K] @ B[N,K]^T.
// 2-term fp16: A split hi/lo, B single. f32 accum. 2-stage cp.async,
// 256 threads = 8 warps (2m x 4n), warp tile 64x32, KC=32, term-major.
// MODE 0: A = x, B = Wq/Wk/Wv (z); out -> fp16 hi/lo [B,H,S,HD] (+Q scale)
// MODE 1: A = ctx, B = Wo; out -> fp32 [M,N] + bias
// ---------------------------------------------------------------------------
#define GP 40                 // smem pitch in fp16 (80 bytes)
#define GT (128 * GP * 2)     // one tile: 10240 bytes
#define GSTAGE (3 * GT)       // one stage (Ah,Al,B): 30720 bytes
#define SMEM_GEMM (2 * GSTAGE)

__device__ __forceinline__ void gemm_issue(uint32_t sb,
    const char* Ah, const char* Al, const char* Bs,
    int m0, int n0, int c, int t)
{
    int lrow = t >> 1, lq = (t & 1) * 2;
    size_t goA = (size_t)(m0 + lrow) * (GK * 2) + (size_t)c * 64 + lq * 16;
    size_t goB = (size_t)(n0 + lrow) * (GK * 2) + (size_t)c * 64 + lq * 16;
    uint32_t soff = lrow * (GP * 2) + lq * 16;
    cpa16(sb + soff,               Ah + goA);
    cpa16(sb + soff + 16,          Ah + goA + 16);
    cpa16(sb + GT + soff,          Al + goA);
    cpa16(sb + GT + soff + 16,     Al + goA + 16);
    cpa16(sb + 2 * GT + soff,      Bs + goB);
    cpa16(sb + 2 * GT + soff + 16, Bs + goB + 16);
}

template <int MODE>
__global__ __launch_bounds__(256, 2)
void mma_gemm_kernel(const float* __restrict__ bias, float* __restrict__ dout)
{
    extern __shared__ char smem[];
    const uint32_t sbase = smem_u32(smem);

    const __half *Ah, *Al, *Bs;
    __half *OutH = nullptr, *OutL = nullptr;
    float oscale = 1.0f;
    if (MODE == 0) {
        Ah = g_x_hi; Al = g_x_lo;
        if (blockIdx.z == 0)      { Bs = g_wqt; OutH = g_qh; OutL = g_ql; oscale = QSCALE; }
        else if (blockIdx.z == 1) { Bs = g_wkt; OutH = g_kh; OutL = nullptr; }
        else                      { Bs = g_wvt; OutH = g_vh; OutL = nullptr; }
    } else {
        Ah = g_ctx_hi; Al = g_ctx_lo; Bs = g_wot;
    }

    const int m0   = blockIdx.y * 128;
    const int n0   = blockIdx.x * 128;
    const int t    = threadIdx.x;
    const int lane = t & 31;
    const int wid  = t >> 5;
    const int wm   = wid >> 2;
    const int wn   = wid & 3;

    float acc[4][4][4] = {};

    const int NC = GK / 32;
    gemm_issue(sbase, (const char*)Ah, (const char*)Al, (const char*)Bs, m0, n0, 0, t);
    CP_COMMIT();

    for (int c = 0; c < NC; c++) {
        if (c + 1 < NC) {
            gemm_issue(sbase + ((c + 1) & 1) * GSTAGE,
                       (const char*)Ah, (const char*)Al, (const char*)Bs,
                       m0, n0, c + 1, t);
            CP_COMMIT();
            CP_WAIT(1);
        } else {
            CP_WAIT(0);
        }
        __syncthreads();

        const uint32_t sb  = sbase + (c & 1) * GSTAGE;
        const uint32_t uAh = sb, uAl = sb + GT, uB = sb + 2 * GT;

        #pragma unroll
        for (int ks = 0; ks < 2; ks++) {
            uint32_t a_h[4][4], a_l[4][4];
            int abyte = (wm * 64 + (lane & 15)) * (GP * 2) + ks * 32 + (lane >> 4) * 16;
            #pragma unroll
            for (int mt = 0; mt < 4; mt++) {
                ldmx4(a_h[mt], uAh + abyte + mt * 16 * (GP * 2));
                ldmx4(a_l[mt], uAl + abyte + mt * 16 * (GP * 2));
            }
            uint32_t b[2][4];
            #pragma unroll
            for (int j = 0; j < 2; j++) {
                int bbyte = (wn * 32 + j * 16 + ((lane >> 4) << 3) + (lane & 7)) * (GP * 2)
                          + ks * 32 + ((lane >> 3) & 1) * 16;
                ldmx4(b[j], uB + bbyte);
            }
            // term A_hi * B
            #pragma unroll
            for (int mt = 0; mt < 4; mt++)
                #pragma unroll
                for (int j = 0; j < 2; j++) {
                    mma16816h(acc[mt][2 * j],     a_h[mt], b[j][0], b[j][1]);
                    mma16816h(acc[mt][2 * j + 1], a_h[mt], b[j][2], b[j][3]);
                }
            // term A_lo * B
            #pragma unroll
            for (int mt = 0; mt < 4; mt++)
                #pragma unroll
                for (int j = 0; j < 2; j++) {
                    mma16816h(acc[mt][2 * j],     a_l[mt], b[j][0], b[j][1]);
                    mma16816h(acc[mt][2 * j + 1], a_l[mt], b[j][2], b[j][3]);
                }
        }
        __syncthreads();
    }

    // Epilogue
    #pragma unroll
    for (int mt = 0; mt < 4; mt++) {
        int mA = m0 + wm * 64 + mt * 16 + (lane >> 2);
        int mB = mA + 8;
        #pragma unroll
        for (int nt = 0; nt < 4; nt++) {
            int n = n0 + wn * 32 + nt * 8 + (lane & 3) * 2;
            float c0 = acc[mt][nt][0], c1 = acc[mt][nt][1];
            float c2 = acc[mt][nt][2], c3 = acc[mt][nt][3];
            if (MODE == 0) {
                c0 *= oscale; c1 *= oscale; c2 *= oscale; c3 *= oscale;
                int h = n >> 6, hd = n & 63;
                {
                    int b = mA >> 11, s = mA & (S_ - 1);
                    size_t o = ((size_t)((b * H_ + h) * S_) + s) * HD_ + hd;
                    unsigned ph, pl;
                    pack_pair_h(c0, c1, ph, pl);
                    *(unsigned*)&OutH[o] = ph;
                    if (OutL) *(unsigned*)&OutL[o] = pl;
                }
                {
                    int b = mB >> 11, s = mB & (S_ - 1);
                    size_t o = ((size_t)((b * H_ + h) * S_) + s) * HD_ + hd;
                    unsigned ph, pl;
                    pack_pair_h(c2, c3, ph, pl);
                    *(unsigned*)&OutH[o] = ph;
                    if (OutL) *(unsigned*)&OutL[o] = pl;
                }
            } else {
                float b0 = bias[n], b1 = bias[n + 1];
                *(float2*)&dout[(size_t)mA * GN + n] = make_float2(c0 + b0, c1 + b1);
                *(float2*)&dout[(size_t)mB * GN + n] = make_float2(c2 + b0, c3 + b1);
            }
        }
    }
}

// ---------------------------------------------------------------------------
// Flash attention (R9 structure): 2-term fp16 (Q split / K single;
// P split / V single), f32 accum, causal, 2-stage cp.async.
// grid (S/64, B*H), 128 threads = 4 warps; warp owns 16 query rows.
// ---------------------------------------------------------------------------
#define AP 72                 // smem pitch in fp16 (144 bytes)
#define AT (64 * AP * 2)      // one tile: 9216 bytes
#define ASTAGE (2 * AT)       // K, V: 18432 bytes
#define SMEM_ATTN (2 * ASTAGE)

__device__ __forceinline__ void attn_issue_kv(uint32_t sb,
    const __half* K, const __half* V, int kb, int t)
{
    const uint4* gk = (const uint4*)(K + (size_t)kb * 64 * HD_);
    const uint4* gv = (const uint4*)(V + (size_t)kb * 64 * HD_);
    #pragma unroll
    for (int p = 0; p < 4; p++) {
        int idx = t + p * 128;
        int row = idx >> 3, q = idx & 7;
        uint32_t soff = row * (AP * 2) + q * 16;
        cpa16(sb + soff,      gk + idx);
        cpa16(sb + AT + soff, gv + idx);
    }
}

__global__ __launch_bounds__(128, 2)
void attn_mma_kernel()
{
    extern __shared__ char smem[];
    const uint32_t sbase = smem_u32(smem);

    // heaviest (largest qb) blocks launch first
    const int qb   = gridDim.x - 1 - blockIdx.x;
    const int bh   = blockIdx.y;
    const int t    = threadIdx.x;
    const int lane = t & 31;
    const int wid  = t >> 5;

    const size_t head_off = (size_t)bh * S_ * HD_;
    const __half* Qh = g_qh + head_off + (size_t)qb * 64 * HD_;
    const __half* Ql = g_ql + head_off + (size_t)qb * 64 * HD_;
    const __half* K  = g_kh + head_off;
    const __half* V  = g_vh + head_off;

    // ---- stage Q (hi,lo) into stage-1 buffers via cp.async (group 0) ----
    {
        uint32_t qsb = sbase + ASTAGE;
        #pragma unroll
        for (int p = 0; p < 4; p++) {
            int idx = t + p * 128;
            int row = idx >> 3, q = idx & 7;
            uint32_t soff = row * (AP * 2) + q * 16;
            cpa16(qsb + soff,      ((const uint4*)Qh) + idx);
            cpa16(qsb + AT + soff, ((const uint4*)Ql) + idx);
        }
        CP_COMMIT();
    }
    // ---- kb=0 K/V into stage 0 (group 1) ----
    attn_issue_kv(sbase, K, V, 0, t);
    CP_COMMIT();

    CP_WAIT(1);
    __syncthreads();

    uint32_t aq_h[4][4], aq_l[4][4];
    {
        uint32_t uQh = sbase + ASTAGE, uQl = sbase + ASTAGE + AT;
        int qbyte = (wid * 16 + (lane & 15)) * (AP * 2) + (lane >> 4) * 16;
        #pragma unroll
        for (int kc = 0; kc < 4; kc++) {
            ldmx4(aq_h[kc], uQh + qbyte + kc * 32);
            ldmx4(aq_l[kc], uQl + qbyte + kc * 32);
        }
    }
    __syncthreads();

    float oAcc[8][4] = {};
    float m0r = -1e30f, m1r = -1e30f;
    float l0 = 0.0f, l1 = 0.0f;

    for (int kb = 0; kb <= qb; kb++) {
        if (kb < qb) {
            attn_issue_kv(sbase + ((kb + 1) & 1) * ASTAGE, K, V, kb + 1, t);
            CP_COMMIT();
            CP_WAIT(1);
        } else {
            CP_WAIT(0);
        }
        __syncthreads();

        const uint32_t sb = sbase + (kb & 1) * ASTAGE;
        const uint32_t uK = sb, uV = sb + AT;

        // ---- S = Q K^T (2-term, term-major) ----
        float sc[8][4] = {};
        #pragma unroll
        for (int kc = 0; kc < 4; kc++) {
            uint32_t b[4][4];
            #pragma unroll
            for (int j = 0; j < 4; j++) {
                int bbyte = (j * 16 + ((lane >> 4) << 3) + (lane & 7)) * (AP * 2)
                          + kc * 32 + ((lane >> 3) & 1) * 16;
                ldmx4(b[j], uK + bbyte);
            }
            #pragma unroll
            for (int j = 0; j < 4; j++) {
                mma16816h(sc[2 * j],     aq_h[kc], b[j][0], b[j][1]);
                mma16816h(sc[2 * j + 1], aq_h[kc], b[j][2], b[j][3]);
            }
            #pragma unroll
            for (int j = 0; j < 4; j++) {
                mma16816h(sc[2 * j],     aq_l[kc], b[j][0], b[j][1]);
                mma16816h(sc[2 * j + 1], aq_l[kc], b[j][2], b[j][3]);
            }
        }

        // ---- causal mask (scores pre-scaled via Q; log2 domain) ----
        if (kb == qb) {
            int r0l = wid * 16 + (lane >> 2);
            #pragma unroll
            for (int nt = 0; nt < 8; nt++) {
                int col = nt * 8 + (lane & 3) * 2;
                if (col > r0l)         sc[nt][0] = -1e30f;
                if (col + 1 > r0l)     sc[nt][1] = -1e30f;
                if (col > r0l + 8)     sc[nt][2] = -1e30f;
                if (col + 1 > r0l + 8) sc[nt][3] = -1e30f;
            }
        }

        // ---- online softmax (base-2) ----
        float mx0 = -1e30f, mx1 = -1e30f;
        #pragma unroll
        for (int nt = 0; nt < 8; nt++) {
            mx0 = fmaxf(mx0, fmaxf(sc[nt][0], sc[nt][1]));
            mx1 = fmaxf(mx1, fmaxf(sc[nt][2], sc[nt][3]));
        }
        mx0 = fmaxf(mx0, __shfl_xor_sync(0xffffffffu, mx0, 1));
        mx0 = fmaxf(mx0, __shfl_xor_sync(0xffffffffu, mx0, 2));
        mx1 = fmaxf(mx1, __shfl_xor_sync(0xffffffffu, mx1, 1));
        mx1 = fmaxf(mx1, __shfl_xor_sync(0xffffffffu, mx1, 2));

        float mn0 = fmaxf(m0r, mx0), mn1 = fmaxf(m1r, mx1);
        float cr0 = ex2(m0r - mn0), cr1 = ex2(m1r - mn1);

        float sum0 = 0.0f, sum1 = 0.0f;
        #pragma unroll
        for (int nt = 0; nt < 8; nt++) {
            float p0 = ex2(sc[nt][0] - mn0);
            float p1 = ex2(sc[nt][1] - mn0);
            float p2 = ex2(sc[nt][2] - mn1);
            float p3 = ex2(sc[nt][3] - mn1);
            sc[nt][0] = p0; sc[nt][1] = p1; sc[nt][2] = p2; sc[nt][3] = p3;
            sum0 += p0 + p1;
            sum1 += p2 + p3;
        }
        sum0 += __shfl_xor_sync(0xffffffffu, sum0, 1);
        sum0 += __shfl_xor_sync(0xffffffffu, sum0, 2);
        sum1 += __shfl_xor_sync(0xffffffffu, sum1, 1);
        sum1 += __shfl_xor_sync(0xffffffffu, sum1, 2);

        l0 = l0 * cr0 + sum0;  m0r = mn0;
        l1 = l1 * cr1 + sum1;  m1r = mn1;

        #pragma unroll
        for (int nt = 0; nt < 8; nt++) {
            oAcc[nt][0] *= cr0; oAcc[nt][1] *= cr0;
            oAcc[nt][2] *= cr1; oAcc[nt][3] *= cr1;
        }

        // ---- O += P V (2-term: P hi/lo, V single; term-major) ----
        #pragma unroll
        for (int kc = 0; kc < 4; kc++) {
            uint32_t pa_h[4], pa_l[4];
            pack_pair_h(sc[2 * kc][0],     sc[2 * kc][1],     pa_h[0], pa_l[0]);
            pack_pair_h(sc[2 * kc][2],     sc[2 * kc][3],     pa_h[1], pa_l[1]);
            pack_pair_h(sc[2 * kc + 1][0], sc[2 * kc + 1][1], pa_h[2], pa_l[2]);
            pack_pair_h(sc[2 * kc + 1][2], sc[2 * kc + 1][3], pa_h[3], pa_l[3]);
            uint32_t v[4][4];
            #pragma unroll
            for (int j = 0; j < 4; j++) {
                int key   = kc * 16 + ((lane >> 3) & 1) * 8 + (lane & 7);
                int hd    = j * 16 + (lane >> 4) * 8;
                int vbyte = key * (AP * 2) + hd * 2;
                ldmx4t(v[j], uV + vbyte);
            }
            #pragma unroll
            for (int j = 0; j < 4; j++) {
                mma16816h(oAcc[2 * j],     pa_h, v[j][0], v[j][1]);
                mma16816h(oAcc[2 * j + 1], pa_h, v[j][2], v[j][3]);
            }
            #pragma unroll
            for (int j = 0; j < 4; j++) {
                mma16816h(oAcc[2 * j],     pa_l, v[j][0], v[j][1]);
                mma16816h(oAcc[2 * j + 1], pa_l, v[j][2], v[j][3]);
            }
        }
        __syncthreads();
    }

    // ---- finalize: ctx hi/lo fp16 [B,S,D] ----
    const float inv0 = 1.0f / l0, inv1 = 1.0f / l1;
    const int b = bh >> 4, h = bh & 15;
    const int r0 = qb * 64 + wid * 16 + (lane >> 2);
    const int r1 = r0 + 8;
    #pragma unroll
    for (int nt = 0; nt < 8; nt++) {
        int hd = nt * 8 + (lane & 3) * 2;
        float v0 = oAcc[nt][0] * inv0, v1 = oAcc[nt][1] * inv0;
        float v2 = oAcc[nt][2] * inv1, v3 = oAcc[nt][3] * inv1;
        size_t o0 = ((size_t)(b * S_ + r0)) * D_ + h * HD_ + hd;
        size_t o1 = ((size_t)(b * S_ + r1)) * D_ + h * HD_ + hd;
        unsigned ph, pl;
        pack_pair_h(v0, v1, ph, pl);
        *(unsigned*)&g_ctx_hi[o0] = ph;
        *(unsigned*)&g_ctx_lo[o0] = pl;
        pack_pair_h(v2, v3, ph, pl);
        *(unsigned*)&g_ctx_hi[o1] = ph;
        *(unsigned*)&g_ctx_lo[o1] = pl;
    }
}

// ---------------------------------------------------------------------------
// fp32 -> (fp16 hi, fp16 lo) split of x
// ---------------------------------------------------------------------------
__global__ void split_x_kernel(const float4* __restrict__ src)
{
    int i = blockIdx.x * blockDim.x + threadIdx.x;
    if (i >= GM * GK / 4) return;
    float4 v = src[i];
    unsigned h0, l0p, h1, l1p;
    pack_pair_h(v.x, v.y, h0, l0p);
    pack_pair_h(v.z, v.w, h1, l1p);
    ((unsigned*)g_x_hi)[i * 2]     = h0;
    ((unsigned*)g_x_hi)[i * 2 + 1] = h1;
    ((unsigned*)g_x_lo)[i * 2]     = l0p;
    ((unsigned*)g_x_lo)[i * 2 + 1] = l1p;
}

// ---------------------------------------------------------------------------
// Batched: W [K,N] fp32 -> Wt [N,K] single fp16 for all 4 weights (blockIdx.z)
// ---------------------------------------------------------------------------
__global__ void transpose_split4_kernel(const float* __restrict__ W0,
                                        const float* __restrict__ W1,
                                        const float* __restrict__ W2,
                                        const float* __restrict__ W3)
{
    __shared__ float tile[32][33];
    const float* W;
    __half* dst;
    switch (blockIdx.z) {
        case 0:  W = W0; dst = g_wqt; break;
        case 1:  W = W1; dst = g_wkt; break;
        case 2:  W = W2; dst = g_wvt; break;
        default: W = W3; dst = g_wot; break;
    }
    const int tx = threadIdx.x, ty = threadIdx.y;
    const int k0 = blockIdx.y * 32;
    const int n0 = blockIdx.x * 32;
    #pragma unroll
    for (int j = 0; j < 4; j++)
        tile[ty + j * 8][tx] = W[(size_t)(k0 + ty + j * 8) * GN + n0 + tx];
    __syncthreads();
    #pragma unroll
    for (int j = 0; j < 4; j++) {
        int n = n0 + ty + j * 8;
        int k = k0 + tx;
        dst[(size_t)n * GK + k] = __float2half_rn(tile[tx][ty + j * 8]);
    }
}

// ---------------------------------------------------------------------------
extern "C" void kernel_launch(void* const* d_in, const int* in_sizes, int n_in,
                              void* d_out, int out_size)
{
    const float* x  = (const float*)d_in[0];
    const float* Wq = (const float*)d_in[1];
    const float* Wk = (const float*)d_in[2];
    const float* Wv = (const float*)d_in[3];
    const float* Wo = (const float*)d_in[4];
    const float* bo = (const float*)d_in[5];
    float*       out = (float*)d_out;

    cudaFuncSetAttribute(mma_gemm_kernel<0>,
                         cudaFuncAttributeMaxDynamicSharedMemorySize, SMEM_GEMM);
    cudaFuncSetAttribute(mma_gemm_kernel<1>,
                         cudaFuncAttributeMaxDynamicSharedMemorySize, SMEM_GEMM);
    cudaFuncSetAttribute(attn_mma_kernel,
                         cudaFuncAttributeMaxDynamicSharedMemorySize, SMEM_ATTN);

    // 1) prep: split x (fp16 hi/lo), transpose weights to single fp16
    split_x_kernel<<<(GM * GK / 4 + 255) / 256, 256>>>((const float4*)x);
    transpose_split4_kernel<<<dim3(GN / 32, GK / 32, 4), dim3(32, 8)>>>(Wq, Wk, Wv, Wo);

    // 2) QKV projections (2-term fp16) -> fp16 [B,H,S,HD] (Q split+scaled)
    mma_gemm_kernel<0><<<dim3(GN / 128, GM / 128, 3), 256, SMEM_GEMM>>>(nullptr, nullptr);

    // 3) attention (2-term fp16) -> ctx fp16 hi/lo
    attn_mma_kernel<<<dim3(S_ / 64, B_ * H_), 128, SMEM_ATTN>>>();

    // 4) output projection + bias (2-term fp16) -> fp32 out
    mma_gemm_kernel<1><<<dim3(GN / 128, GM / 128, 1), 256, SMEM_GEMM>>>(bo, out);
}

// round 14
// speedup vs baseline: 2.6531x; 1.1877x over previous
#include <cuda_runtime.h>
#include <cuda_bf16.h>
#include <cuda_fp16.h>
#include <cstdint>

// Problem dims
#define B_  2
#define S_  2048
#define D_  1024
#define H_  16
#define HD_ 64
#define GM  (B_ * S_)   // 4096
#define GN  D_          // 1024
#define GK  D_          // 1024

// softmax scale folded into Q: 1/sqrt(64) * log2(e)
#define QSCALE 0.18033688011112043f

// ---------------------------------------------------------------------------
// Scratch (__device__ globals; allocation-free rule)
// ---------------------------------------------------------------------------
__device__ __half g_x_hi[GM * GK];
__device__ __half g_x_lo[GM * GK];
__device__ __half g_qh[B_ * H_ * S_ * HD_];   // [B,H,S,HD] (Q pre-scaled, split)
__device__ __half g_ql[B_ * H_ * S_ * HD_];
__device__ __half g_kh[B_ * H_ * S_ * HD_];   // K single fp16
__device__ __half g_vh[B_ * H_ * S_ * HD_];   // V single fp16
__device__ __half g_ctx[GM * GK];             // [B,S,D] single fp16
// transposed weights [N, K] K-major, single fp16
__device__ __half g_wqt[GN * GK];
__device__ __half g_wkt[GN * GK];
__device__ __half g_wvt[GN * GK];
__device__ __half g_wot[GN * GK];

// ---------------------------------------------------------------------------
// Warp-MMA / async-copy primitives
// ---------------------------------------------------------------------------
__device__ __forceinline__ uint32_t smem_u32(const void* p) {
    uint32_t a;
    asm("{ .reg .u64 t; cvta.to.shared.u64 t, %1; cvt.u32.u64 %0, t; }"
        : "=r"(a) : "l"(p));
    return a;
}

// fp16 in, f32 acc
__device__ __forceinline__ void mma16816h(float* c, const uint32_t* a,
                                          uint32_t b0, uint32_t b1) {
    asm volatile(
        "mma.sync.aligned.m16n8k16.row.col.f32.f16.f16.f32 "
        "{%0,%1,%2,%3}, {%4,%5,%6,%7}, {%8,%9}, {%0,%1,%2,%3};"
        : "+f"(c[0]), "+f"(c[1]), "+f"(c[2]), "+f"(c[3])
        : "r"(a[0]), "r"(a[1]), "r"(a[2]), "r"(a[3]), "r"(b0), "r"(b1));
}

__device__ __forceinline__ void ldmx4(uint32_t* r, uint32_t addr) {
    asm volatile("ldmatrix.sync.aligned.m8n8.x4.shared.b16 {%0,%1,%2,%3}, [%4];"
        : "=r"(r[0]), "=r"(r[1]), "=r"(r[2]), "=r"(r[3]) : "r"(addr));
}

__device__ __forceinline__ void ldmx4t(uint32_t* r, uint32_t addr) {
    asm volatile("ldmatrix.sync.aligned.m8n8.x4.trans.shared.b16 {%0,%1,%2,%3}, [%4];"
        : "=r"(r[0]), "=r"(r[1]), "=r"(r[2]), "=r"(r[3]) : "r"(addr));
}

__device__ __forceinline__ void cpa16(uint32_t s, const void* g) {
    asm volatile("cp.async.cg.shared.global [%0], [%1], 16;"
                 :: "r"(s), "l"(g) : "memory");
}
#define CP_COMMIT() asm volatile("cp.async.commit_group;" ::: "memory")
#define CP_WAIT(n)  asm volatile("cp.async.wait_group %0;" :: "n"(n) : "memory")

__device__ __forceinline__ float ex2(float x) {
    float r;
    asm("ex2.approx.f32 %0, %1;" : "=f"(r) : "f"(x));
    return r;
}

// fp16 hi/lo pack
__device__ __forceinline__ void pack_pair_h(float x, float y, unsigned& hi, unsigned& lo) {
    __half2 h = __floats2half2_rn(x, y);
    hi = *reinterpret_cast<unsigned*>(&h);
    float xr = x - __half2float(__low2half(h));
    float yr = y - __half2float(__high2half(h));
    __half2 l = __floats2half2_rn(xr, yr);
    lo = *reinterpret_cast<unsigned*>(&l);
}
__device__ __forceinline__ unsigned pack_h2(float x, float y) {
    __half2 h = __floats2half2_rn(x, y);
    return *reinterpret_cast<unsigned*>(&h);
}

// ---------------------------------------------------------------------------
// GEMM: C[128,128] tile of A[M,K] @ B[N,K]^T, fp16 in / f32 acc.
// 2-stage cp.async, 256 threads = 8 warps (2m x 4n), warp tile 64x32, KC=32.
// MODE 0: Q proj — A = x split hi/lo (2-term), B = Wq; out fp16 hi/lo +QSCALE
// MODE 1: K/V proj (z) — A = x single (1-term), B = Wk/Wv; out fp16 single
// MODE 2: out proj — A = ctx single (1-term), B = Wo; out fp32 + bias
// ---------------------------------------------------------------------------
#define GP 40                 // smem pitch in fp16 (80 bytes)
#define GT (128 * GP * 2)     // one tile: 10240 bytes

template <int MODE>
__global__ __launch_bounds__(256, 2)
void mma_gemm_kernel(const float* __restrict__ bias, float* __restrict__ dout)
{
    constexpr int NT  = (MODE == 0) ? 3 : 2;  // tiles per stage
    constexpr int STG = NT * GT;
    extern __shared__ char smem[];
    const uint32_t sbase = smem_u32(smem);

    const __half *Ah, *Al = nullptr, *Bs;
    __half *OutH = nullptr, *OutL = nullptr;
    if (MODE == 0) {
        Ah = g_x_hi; Al = g_x_lo; Bs = g_wqt; OutH = g_qh; OutL = g_ql;
    } else if (MODE == 1) {
        Ah = g_x_hi;
        if (blockIdx.z == 0) { Bs = g_wkt; OutH = g_kh; }
        else                 { Bs = g_wvt; OutH = g_vh; }
    } else {
        Ah = g_ctx; Bs = g_wot;
    }

    const int m0   = blockIdx.y * 128;
    const int n0   = blockIdx.x * 128;
    const int t    = threadIdx.x;
    const int lane = t & 31;
    const int wid  = t >> 5;
    const int wm   = wid >> 2;
    const int wn   = wid & 3;

    const int lrow = t >> 1, lq = (t & 1) * 2;
    const uint32_t soff = lrow * (GP * 2) + lq * 16;

    auto issue = [&](uint32_t sb, int c) {
        size_t goA = (size_t)(m0 + lrow) * (GK * 2) + (size_t)c * 64 + lq * 16;
        size_t goB = (size_t)(n0 + lrow) * (GK * 2) + (size_t)c * 64 + lq * 16;
        cpa16(sb + soff,      (const char*)Ah + goA);
        cpa16(sb + soff + 16, (const char*)Ah + goA + 16);
        if (MODE == 0) {
            cpa16(sb + GT + soff,      (const char*)Al + goA);
            cpa16(sb + GT + soff + 16, (const char*)Al + goA + 16);
        }
        cpa16(sb + (NT - 1) * GT + soff,      (const char*)Bs + goB);
        cpa16(sb + (NT - 1) * GT + soff + 16, (const char*)Bs + goB + 16);
    };

    float acc[4][4][4] = {};

    const int NC = GK / 32;
    issue(sbase, 0);
    CP_COMMIT();

    for (int c = 0; c < NC; c++) {
        if (c + 1 < NC) {
            issue(sbase + ((c + 1) & 1) * STG, c + 1);
            CP_COMMIT();
            CP_WAIT(1);
        } else {
            CP_WAIT(0);
        }
        __syncthreads();

        const uint32_t sb  = sbase + (c & 1) * STG;
        const uint32_t uAh = sb;
        const uint32_t uAl = sb + GT;                 // MODE 0 only
        const uint32_t uB  = sb + (NT - 1) * GT;

        #pragma unroll
        for (int ks = 0; ks < 2; ks++) {
            uint32_t a_h[4][4], a_l[4][4];
            int abyte = (wm * 64 + (lane & 15)) * (GP * 2) + ks * 32 + (lane >> 4) * 16;
            #pragma unroll
            for (int mt = 0; mt < 4; mt++) {
                ldmx4(a_h[mt], uAh + abyte + mt * 16 * (GP * 2));
                if (MODE == 0)
                    ldmx4(a_l[mt], uAl + abyte + mt * 16 * (GP * 2));
            }
            uint32_t b[2][4];
            #pragma unroll
            for (int j = 0; j < 2; j++) {
                int bbyte = (wn * 32 + j * 16 + ((lane >> 4) << 3) + (lane & 7)) * (GP * 2)
                          + ks * 32 + ((lane >> 3) & 1) * 16;
                ldmx4(b[j], uB + bbyte);
            }
            #pragma unroll
            for (int mt = 0; mt < 4; mt++)
                #pragma unroll
                for (int j = 0; j < 2; j++) {
                    mma16816h(acc[mt][2 * j],     a_h[mt], b[j][0], b[j][1]);
                    mma16816h(acc[mt][2 * j + 1], a_h[mt], b[j][2], b[j][3]);
                }
            if (MODE == 0) {
                #pragma unroll
                for (int mt = 0; mt < 4; mt++)
                    #pragma unroll
                    for (int j = 0; j < 2; j++) {
                        mma16816h(acc[mt][2 * j],     a_l[mt], b[j][0], b[j][1]);
                        mma16816h(acc[mt][2 * j + 1], a_l[mt], b[j][2], b[j][3]);
                    }
            }
        }
        __syncthreads();
    }

    // Epilogue
    #pragma unroll
    for (int mt = 0; mt < 4; mt++) {
        int mA = m0 + wm * 64 + mt * 16 + (lane >> 2);
        int mB = mA + 8;
        #pragma unroll
        for (int nt = 0; nt < 4; nt++) {
            int n = n0 + wn * 32 + nt * 8 + (lane & 3) * 2;
            float c0 = acc[mt][nt][0], c1 = acc[mt][nt][1];
            float c2 = acc[mt][nt][2], c3 = acc[mt][nt][3];
            if (MODE == 0) {
                c0 *= QSCALE; c1 *= QSCALE; c2 *= QSCALE; c3 *= QSCALE;
                int h = n >> 6, hd = n & 63;
                {
                    int b = mA >> 11, s = mA & (S_ - 1);
                    size_t o = ((size_t)((b * H_ + h) * S_) + s) * HD_ + hd;
                    unsigned ph, pl;
                    pack_pair_h(c0, c1, ph, pl);
                    *(unsigned*)&OutH[o] = ph;
                    *(unsigned*)&OutL[o] = pl;
                }
                {
                    int b = mB >> 11, s = mB & (S_ - 1);
                    size_t o = ((size_t)((b * H_ + h) * S_) + s) * HD_ + hd;
                    unsigned ph, pl;
                    pack_pair_h(c2, c3, ph, pl);
                    *(unsigned*)&OutH[o] = ph;
                    *(unsigned*)&OutL[o] = pl;
                }
            } else if (MODE == 1) {
                int h = n >> 6, hd = n & 63;
                {
                    int b = mA >> 11, s = mA & (S_ - 1);
                    size_t o = ((size_t)((b * H_ + h) * S_) + s) * HD_ + hd;
                    *(unsigned*)&OutH[o] = pack_h2(c0, c1);
                }
                {
                    int b = mB >> 11, s = mB & (S_ - 1);
                    size_t o = ((size_t)((b * H_ + h) * S_) + s) * HD_ + hd;
                    *(unsigned*)&OutH[o] = pack_h2(c2, c3);
                }
            } else {
                float b0 = bias[n], b1 = bias[n + 1];
                *(float2*)&dout[(size_t)mA * GN + n] = make_float2(c0 + b0, c1 + b1);
                *(float2*)&dout[(size_t)mB * GN + n] = make_float2(c2 + b0, c3 + b1);
            }
        }
    }
}

// ---------------------------------------------------------------------------
// Flash attention (R12 structure, unchanged): 2-term fp16 (Q split / K single;
// P split / V single), f32 accum, causal, 2-stage cp.async.
// ctx now written as SINGLE fp16.
// grid (S/64, B*H), 128 threads = 4 warps; warp owns 16 query rows.
// ---------------------------------------------------------------------------
#define AP 72                 // smem pitch in fp16 (144 bytes)
#define AT (64 * AP * 2)      // one tile: 9216 bytes
#define ASTAGE (2 * AT)       // K, V: 18432 bytes
#define SMEM_ATTN (2 * ASTAGE)

__device__ __forceinline__ void attn_issue_kv(uint32_t sb,
    const __half* K, const __half* V, int kb, int t)
{
    const uint4* gk = (const uint4*)(K + (size_t)kb * 64 * HD_);
    const uint4* gv = (const uint4*)(V + (size_t)kb * 64 * HD_);
    #pragma unroll
    for (int p = 0; p < 4; p++) {
        int idx = t + p * 128;
        int row = idx >> 3, q = idx & 7;
        uint32_t soff = row * (AP * 2) + q * 16;
        cpa16(sb + soff,      gk + idx);
        cpa16(sb + AT + soff, gv + idx);
    }
}

__global__ __launch_bounds__(128, 2)
void attn_mma_kernel()
{
    extern __shared__ char smem[];
    const uint32_t sbase = smem_u32(smem);

    const int qb   = gridDim.x - 1 - blockIdx.x;
    const int bh   = blockIdx.y;
    const int t    = threadIdx.x;
    const int lane = t & 31;
    const int wid  = t >> 5;

    const size_t head_off = (size_t)bh * S_ * HD_;
    const __half* Qh = g_qh + head_off + (size_t)qb * 64 * HD_;
    const __half* Ql = g_ql + head_off + (size_t)qb * 64 * HD_;
    const __half* K  = g_kh + head_off;
    const __half* V  = g_vh + head_off;

    // ---- stage Q (hi,lo) into stage-1 buffers via cp.async (group 0) ----
    {
        uint32_t qsb = sbase + ASTAGE;
        #pragma unroll
        for (int p = 0; p < 4; p++) {
            int idx = t + p * 128;
            int row = idx >> 3, q = idx & 7;
            uint32_t soff = row * (AP * 2) + q * 16;
            cpa16(qsb + soff,      ((const uint4*)Qh) + idx);
            cpa16(qsb + AT + soff, ((const uint4*)Ql) + idx);
        }
        CP_COMMIT();
    }
    attn_issue_kv(sbase, K, V, 0, t);
    CP_COMMIT();

    CP_WAIT(1);
    __syncthreads();

    uint32_t aq_h[4][4], aq_l[4][4];
    {
        uint32_t uQh = sbase + ASTAGE, uQl = sbase + ASTAGE + AT;
        int qbyte = (wid * 16 + (lane & 15)) * (AP * 2) + (lane >> 4) * 16;
        #pragma unroll
        for (int kc = 0; kc < 4; kc++) {
            ldmx4(aq_h[kc], uQh + qbyte + kc * 32);
            ldmx4(aq_l[kc], uQl + qbyte + kc * 32);
        }
    }
    __syncthreads();

    float oAcc[8][4] = {};
    float m0r = -1e30f, m1r = -1e30f;
    float l0 = 0.0f, l1 = 0.0f;

    for (int kb = 0; kb <= qb; kb++) {
        if (kb < qb) {
            attn_issue_kv(sbase + ((kb + 1) & 1) * ASTAGE, K, V, kb + 1, t);
            CP_COMMIT();
            CP_WAIT(1);
        } else {
            CP_WAIT(0);
        }
        __syncthreads();

        const uint32_t sb = sbase + (kb & 1) * ASTAGE;
        const uint32_t uK = sb, uV = sb + AT;

        // ---- S = Q K^T (2-term, term-major) ----
        float sc[8][4] = {};
        #pragma unroll
        for (int kc = 0; kc < 4; kc++) {
            uint32_t b[4][4];
            #pragma unroll
            for (int j = 0; j < 4; j++) {
                int bbyte = (j * 16 + ((lane >> 4) << 3) + (lane & 7)) * (AP * 2)
                          + kc * 32 + ((lane >> 3) & 1) * 16;
                ldmx4(b[j], uK + bbyte);
            }
            #pragma unroll
            for (int j = 0; j < 4; j++) {
                mma16816h(sc[2 * j],     aq_h[kc], b[j][0], b[j][1]);
                mma16816h(sc[2 * j + 1], aq_h[kc], b[j][2], b[j][3]);
            }
            #pragma unroll
            for (int j = 0; j < 4; j++) {
                mma16816h(sc[2 * j],     aq_l[kc], b[j][0], b[j][1]);
                mma16816h(sc[2 * j + 1], aq_l[kc], b[j][2], b[j][3]);
            }
        }

        // ---- causal mask ----
        if (kb == qb) {
            int r0l = wid * 16 + (lane >> 2);
            #pragma unroll
            for (int nt = 0; nt < 8; nt++) {
                int col = nt * 8 + (lane & 3) * 2;
                if (col > r0l)         sc[nt][0] = -1e30f;
                if (col + 1 > r0l)     sc[nt][1] = -1e30f;
                if (col > r0l + 8)     sc[nt][2] = -1e30f;
                if (col + 1 > r0l + 8) sc[nt][3] = -1e30f;
            }
        }

        // ---- online softmax (base-2) ----
        float mx0 = -1e30f, mx1 = -1e30f;
        #pragma unroll
        for (int nt = 0; nt < 8; nt++) {
            mx0 = fmaxf(mx0, fmaxf(sc[nt][0], sc[nt][1]));
            mx1 = fmaxf(mx1, fmaxf(sc[nt][2], sc[nt][3]));
        }
        mx0 = fmaxf(mx0, __shfl_xor_sync(0xffffffffu, mx0, 1));
        mx0 = fmaxf(mx0, __shfl_xor_sync(0xffffffffu, mx0, 2));
        mx1 = fmaxf(mx1, __shfl_xor_sync(0xffffffffu, mx1, 1));
        mx1 = fmaxf(mx1, __shfl_xor_sync(0xffffffffu, mx1, 2));

        float mn0 = fmaxf(m0r, mx0), mn1 = fmaxf(m1r, mx1);
        float cr0 = ex2(m0r - mn0), cr1 = ex2(m1r - mn1);

        float sum0 = 0.0f, sum1 = 0.0f;
        #pragma unroll
        for (int nt = 0; nt < 8; nt++) {
            float p0 = ex2(sc[nt][0] - mn0);
            float p1 = ex2(sc[nt][1] - mn0);
            float p2 = ex2(sc[nt][2] - mn1);
            float p3 = ex2(sc[nt][3] - mn1);
            sc[nt][0] = p0; sc[nt][1] = p1; sc[nt][2] = p2; sc[nt][3] = p3;
            sum0 += p0 + p1;
            sum1 += p2 + p3;
        }
        sum0 += __shfl_xor_sync(0xffffffffu, sum0, 1);
        sum0 += __shfl_xor_sync(0xffffffffu, sum0, 2);
        sum1 += __shfl_xor_sync(0xffffffffu, sum1, 1);
        sum1 += __shfl_xor_sync(0xffffffffu, sum1, 2);

        l0 = l0 * cr0 + sum0;  m0r = mn0;
        l1 = l1 * cr1 + sum1;  m1r = mn1;

        #pragma unroll
        for (int nt = 0; nt < 8; nt++) {
            oAcc[nt][0] *= cr0; oAcc[nt][1] *= cr0;
            oAcc[nt][2] *= cr1; oAcc[nt][3] *= cr1;
        }

        // ---- O += P V (2-term: P hi/lo, V single; term-major) ----
        #pragma unroll
        for (int kc = 0; kc < 4; kc++) {
            uint32_t pa_h[4], pa_l[4];
            pack_pair_h(sc[2 * kc][0],     sc[2 * kc][1],     pa_h[0], pa_l[0]);
            pack_pair_h(sc[2 * kc][2],     sc[2 * kc][3],     pa_h[1], pa_l[1]);
            pack_pair_h(sc[2 * kc + 1][0], sc[2 * kc + 1][1], pa_h[2], pa_l[2]);
            pack_pair_h(sc[2 * kc + 1][2], sc[2 * kc + 1][3], pa_h[3], pa_l[3]);
            uint32_t v[4][4];
            #pragma unroll
            for (int j = 0; j < 4; j++) {
                int key   = kc * 16 + ((lane >> 3) & 1) * 8 + (lane & 7);
                int hd    = j * 16 + (lane >> 4) * 8;
                int vbyte = key * (AP * 2) + hd * 2;
                ldmx4t(v[j], uV + vbyte);
            }
            #pragma unroll
            for (int j = 0; j < 4; j++) {
                mma16816h(oAcc[2 * j],     pa_h, v[j][0], v[j][1]);
                mma16816h(oAcc[2 * j + 1], pa_h, v[j][2], v[j][3]);
            }
            #pragma unroll
            for (int j = 0; j < 4; j++) {
                mma16816h(oAcc[2 * j],     pa_l, v[j][0], v[j][1]);
                mma16816h(oAcc[2 * j + 1], pa_l, v[j][2], v[j][3]);
            }
        }
        __syncthreads();
    }

    // ---- finalize: ctx single fp16 [B,S,D] ----
    const float inv0 = 1.0f / l0, inv1 = 1.0f / l1;
    const int b = bh >> 4, h = bh & 15;
    const int r0 = qb * 64 + wid * 16 + (lane >> 2);
    const int r1 = r0 + 8;
    #pragma unroll
    for (int nt = 0; nt < 8; nt++) {
        int hd = nt * 8 + (lane & 3) * 2;
        float v0 = oAcc[nt][0] * inv0, v1 = oAcc[nt][1] * inv0;
        float v2 = oAcc[nt][2] * inv1, v3 = oAcc[nt][3] * inv1;
        size_t o0 = ((size_t)(b * S_ + r0)) * D_ + h * HD_ + hd;
        size_t o1 = ((size_t)(b * S_ + r1)) * D_ + h * HD_ + hd;
        *(unsigned*)&g_ctx[o0] = pack_h2(v0, v1);
        *(unsigned*)&g_ctx[o1] = pack_h2(v2, v3);
    }
}

// ---------------------------------------------------------------------------
// fp32 -> (fp16 hi, fp16 lo) split of x
// ---------------------------------------------------------------------------
__global__ void split_x_kernel(const float4* __restrict__ src)
{
    int i = blockIdx.x * blockDim.x + threadIdx.x;
    if (i >= GM * GK / 4) return;
    float4 v = src[i];
    unsigned h0, l0p, h1, l1p;
    pack_pair_h(v.x, v.y, h0, l0p);
    pack_pair_h(v.z, v.w, h1, l1p);
    ((unsigned*)g_x_hi)[i * 2]     = h0;
    ((unsigned*)g_x_hi)[i * 2 + 1] = h1;
    ((unsigned*)g_x_lo)[i * 2]     = l0p;
    ((unsigned*)g_x_lo)[i * 2 + 1] = l1p;
}

// ---------------------------------------------------------------------------
// Batched: W [K,N] fp32 -> Wt [N,K] single fp16 for all 4 weights (blockIdx.z)
// ---------------------------------------------------------------------------
__global__ void transpose_split4_kernel(const float* __restrict__ W0,
                                        const float* __restrict__ W1,
                                        const float* __restrict__ W2,
                                        const float* __restrict__ W3)
{
    __shared__ float tile[32][33];
    const float* W;
    __half* dst;
    switch (blockIdx.z) {
        case 0:  W = W0; dst = g_wqt; break;
        case 1:  W = W1; dst = g_wkt; break;
        case 2:  W = W2; dst = g_wvt; break;
        default: W = W3; dst = g_wot; break;
    }
    const int tx = threadIdx.x, ty = threadIdx.y;
    const int k0 = blockIdx.y * 32;
    const int n0 = blockIdx.x * 32;
    #pragma unroll
    for (int j = 0; j < 4; j++)
        tile[ty + j * 8][tx] = W[(size_t)(k0 + ty + j * 8) * GN + n0 + tx];
    __syncthreads();
    #pragma unroll
    for (int j = 0; j < 4; j++) {
        int n = n0 + ty + j * 8;
        int k = k0 + tx;
        dst[(size_t)n * GK + k] = __float2half_rn(tile[tx][ty + j * 8]);
    }
}

// ---------------------------------------------------------------------------
extern "C" void kernel_launch(void* const* d_in, const int* in_sizes, int n_in,
                              void* d_out, int out_size)
{
    const float* x  = (const float*)d_in[0];
    const float* Wq = (const float*)d_in[1];
    const float* Wk = (const float*)d_in[2];
    const float* Wv = (const float*)d_in[3];
    const float* Wo = (const float*)d_in[4];
    const float* bo = (const float*)d_in[5];
    float*       out = (float*)d_out;

    cudaFuncSetAttribute(mma_gemm_kernel<0>,
                         cudaFuncAttributeMaxDynamicSharedMemorySize, 2 * 3 * GT);
    cudaFuncSetAttribute(mma_gemm_kernel<1>,
                         cudaFuncAttributeMaxDynamicSharedMemorySize, 2 * 2 * GT);
    cudaFuncSetAttribute(mma_gemm_kernel<2>,
                         cudaFuncAttributeMaxDynamicSharedMemorySize, 2 * 2 * GT);
    cudaFuncSetAttribute(attn_mma_kernel,
                         cudaFuncAttributeMaxDynamicSharedMemorySize, SMEM_ATTN);

    // 1) prep: split x (fp16 hi/lo), transpose weights to single fp16
    split_x_kernel<<<(GM * GK / 4 + 255) / 256, 256>>>((const float4*)x);
    transpose_split4_kernel<<<dim3(GN / 32, GK / 32, 4), dim3(32, 8)>>>(Wq, Wk, Wv, Wo);

    // 2) Q projection (2-term) -> fp16 hi/lo, pre-scaled
    mma_gemm_kernel<0><<<dim3(GN / 128, GM / 128, 1), 256, 2 * 3 * GT>>>(nullptr, nullptr);
    // 2b) K/V projections (1-term) -> fp16 single
    mma_gemm_kernel<1><<<dim3(GN / 128, GM / 128, 2), 256, 2 * 2 * GT>>>(nullptr, nullptr);

    // 3) attention (2-term fp16) -> ctx single fp16
    attn_mma_kernel<<<dim3(S_ / 64, B_ * H_), 128, SMEM_ATTN>>>();

    // 4) output projection (1-term) + bias -> fp32 out
    mma_gemm_kernel<2><<<dim3(GN / 128, GM / 128, 1), 256, 2 * 2 * GT>>>(bo, out);
}